// round 5
// baseline (speedup 1.0000x reference)
#include <cuda_runtime.h>
#include <cuda_bf16.h>
#include <math.h>

// ---------------------------------------------------------------------------
// LLaMA attention block — deliberately dumb bisection build.
//   x:[2048,4096] wq:[4096,4096] wk,wv:[4096,1024] wo:[4096,4096]
//   out:[2048,4096] fp32
// Every stage is the simplest possible implementation:
//   naive GEMM (1 thread / output element), RoPE with fp64 trig,
//   naive-parallel attention (validated twice), naive GEMM for out-proj.
// ---------------------------------------------------------------------------

#define T_SEQ   2048
#define D_MODEL 4096
#define KV_DIM  1024
#define N_HEADS 32
#define HD      128
#define SCALE   0.08838834764831845f   // 1/sqrt(128)

// Scratch (device globals; allocation-free rule)
__device__ float g_Q [T_SEQ * D_MODEL];
__device__ float g_K [T_SEQ * KV_DIM];
__device__ float g_V [T_SEQ * KV_DIM];
__device__ float g_AO[T_SEQ * D_MODEL];

// ---------------------------------------------------------------------------
// Naive GEMM: C[m][n] = sum_k A[m][k] * B[k][n].  One thread per (m,n).
// Warp covers 32 consecutive n at fixed m: A broadcast, B coalesced.
// ---------------------------------------------------------------------------
__global__ __launch_bounds__(256)
void gemm_naive(const float* __restrict__ A, const float* __restrict__ B,
                float* __restrict__ C, int M, int N, int K)
{
    const int n = blockIdx.x * 32 + (threadIdx.x & 31);
    const int m = blockIdx.y * 8  + (threadIdx.x >> 5);
    if (m >= M || n >= N) return;

    const float* a = A + (size_t)m * K;
    const float* b = B + n;
    float acc = 0.f;
    for (int k = 0; k < K; k++)
        acc += a[k] * b[(size_t)k * N];
    C[(size_t)m * N + n] = acc;
}

// ---------------------------------------------------------------------------
// RoPE, fresh derivation, fp64 trig.  One block per position t.
//   For head h, pair j (0..63), f_j = 10000^{-j/64}, ang = t * f_j:
//     y[j]    = v[j]   *cos - v[j+64]*sin
//     y[j+64] = v[j+64]*cos + v[j]   *sin
// Applied to Q (heads 0..31, row stride 4096) and K (heads 0..7, stride 1024).
// ---------------------------------------------------------------------------
__global__ __launch_bounds__(256)
void rope2(float* __restrict__ Q, float* __restrict__ K)
{
    const int t = blockIdx.x;
    for (int p = threadIdx.x; p < 40 * 64; p += blockDim.x) {
        const int h = p >> 6;     // 0..39
        const int j = p & 63;     // 0..63

        const double fj  = pow(10000.0, -(double)j / 64.0);
        const double ang = (double)t * fj;
        const float  c   = (float)cos(ang);
        const float  s   = (float)sin(ang);

        float* row;
        if (h < N_HEADS) row = Q + (size_t)t * D_MODEL + h * HD;
        else             row = K + (size_t)t * KV_DIM + (h - N_HEADS) * HD;

        const float v0 = row[j];
        const float v1 = row[j + 64];
        row[j]      = v0 * c - v1 * s;
        row[j + 64] = v1 * c + v0 * s;
    }
}

// ---------------------------------------------------------------------------
// Attention, naive-parallel (unchanged; validated against independent flash
// implementation in R1/R2).  One block per (t, head).
// ---------------------------------------------------------------------------
__device__ __forceinline__ float warp_max(float v) {
#pragma unroll
    for (int o = 16; o > 0; o >>= 1)
        v = fmaxf(v, __shfl_xor_sync(0xffffffffu, v, o));
    return v;
}
__device__ __forceinline__ float warp_sum(float v) {
#pragma unroll
    for (int o = 16; o > 0; o >>= 1)
        v += __shfl_xor_sync(0xffffffffu, v, o);
    return v;
}

__global__ __launch_bounds__(128)
void attn_naive(const float* __restrict__ Q, const float* __restrict__ K,
                const float* __restrict__ V, float* __restrict__ AO)
{
    __shared__ float qs[HD];
    __shared__ float sc[T_SEQ];
    __shared__ float red[4];

    const int tid  = threadIdx.x;
    const int lane = tid & 31;
    const int wid  = tid >> 5;
    const int t    = blockIdx.x;
    const int h    = blockIdx.y;
    const int kh   = h >> 2;            // GQA: q head h -> kv head h/4

    qs[tid] = Q[(size_t)t * D_MODEL + h * HD + tid] * SCALE;
    __syncthreads();

    const float4* q4 = (const float4*)qs;
    for (int k = tid; k <= t; k += 128) {
        const float4* K4 = (const float4*)(K + (size_t)k * KV_DIM + kh * HD);
        float acc = 0.f;
#pragma unroll
        for (int d = 0; d < HD / 4; d++) {
            float4 qv = q4[d];
            float4 kv = K4[d];
            acc += qv.x * kv.x + qv.y * kv.y + qv.z * kv.z + qv.w * kv.w;
        }
        sc[k] = acc;
    }
    __syncthreads();

    float m = -1e30f;
    for (int k = tid; k <= t; k += 128) m = fmaxf(m, sc[k]);
    m = warp_max(m);
    if (lane == 0) red[wid] = m;
    __syncthreads();
    m = fmaxf(fmaxf(red[0], red[1]), fmaxf(red[2], red[3]));
    __syncthreads();

    float s = 0.f;
    for (int k = tid; k <= t; k += 128) {
        float e = __expf(sc[k] - m);
        sc[k] = e;
        s += e;
    }
    s = warp_sum(s);
    if (lane == 0) red[wid] = s;
    __syncthreads();
    s = red[0] + red[1] + red[2] + red[3];

    const float* Vc = V + kh * HD + tid;
    float o = 0.f;
#pragma unroll 4
    for (int k = 0; k <= t; k++)
        o += sc[k] * Vc[(size_t)k * KV_DIM];

    AO[(size_t)t * D_MODEL + h * HD + tid] = o / s;
}

// ---------------------------------------------------------------------------
// launch — plain signature order: x, wq, wk, wv, wo
// ---------------------------------------------------------------------------
extern "C" void kernel_launch(void* const* d_in, const int* in_sizes, int n_in,
                              void* d_out, int out_size)
{
    const float* x  = (const float*)d_in[0];
    const float* wq = (const float*)d_in[1];
    const float* wk = (const float*)d_in[2];
    const float* wv = (const float*)d_in[3];
    const float* wo = (const float*)d_in[4];
    float* out = (float*)d_out;

    float *Qp, *Kp, *Vp, *Ap;
    cudaGetSymbolAddress((void**)&Qp, g_Q);
    cudaGetSymbolAddress((void**)&Kp, g_K);
    cudaGetSymbolAddress((void**)&Vp, g_V);
    cudaGetSymbolAddress((void**)&Ap, g_AO);

    // projections (naive GEMM)
    gemm_naive<<<dim3(D_MODEL / 32, T_SEQ / 8), 256>>>(x, wq, Qp, T_SEQ, D_MODEL, D_MODEL);
    gemm_naive<<<dim3(KV_DIM / 32, T_SEQ / 8), 256>>>(x, wk, Kp, T_SEQ, KV_DIM, D_MODEL);
    gemm_naive<<<dim3(KV_DIM / 32, T_SEQ / 8), 256>>>(x, wv, Vp, T_SEQ, KV_DIM, D_MODEL);

    // RoPE (fp64 trig, fresh implementation)
    rope2<<<T_SEQ, 256>>>(Qp, Kp);

    // attention
    attn_naive<<<dim3(T_SEQ, N_HEADS), 128>>>(Qp, Kp, Vp, Ap);

    // output projection
    gemm_naive<<<dim3(D_MODEL / 32, T_SEQ / 8), 256>>>(Ap, wo, out, T_SEQ, D_MODEL, D_MODEL);
}

// round 6
// speedup vs baseline: 3.3208x; 3.3208x over previous
#include <cuda_runtime.h>
#include <cuda_bf16.h>
#include <math.h>

// ---------------------------------------------------------------------------
// LLaMA attention block, fp32.
//   x:[2048,4096] wq:[4096,4096] wk,wv:[4096,1024] wo:[4096,4096]
//   out:[2048,4096] fp32
// Pipeline: tiled SGEMM (q,k,v) -> RoPE(fp64 trig) -> flash attention -> SGEMM(o)
// ---------------------------------------------------------------------------

#define T_SEQ   2048
#define D_MODEL 4096
#define KV_DIM  1024
#define N_HEADS 32
#define HD      128
#define SCALE   0.08838834764831845f   // 1/sqrt(128)

// Scratch (device globals; allocation-free rule)
__device__ float g_Q [T_SEQ * D_MODEL];
__device__ float g_K [T_SEQ * KV_DIM];
__device__ float g_V [T_SEQ * KV_DIM];
__device__ float g_AO[T_SEQ * D_MODEL];

// ---------------------------------------------------------------------------
// Tiled SGEMM: C[M,N] = A[M,K] * B[K,N].
// BM=BN=128, BK=16, 256 threads, 8x8 per thread, register prefetch.
// ---------------------------------------------------------------------------
__global__ __launch_bounds__(256)
void sgemm_t(const float* __restrict__ A, const float* __restrict__ B,
             float* __restrict__ C, int M, int N, int K)
{
    __shared__ float As[16][132];   // As[k][m], padded
    __shared__ float Bs[16][132];   // Bs[k][n], padded

    const int tid = threadIdx.x;
    const int tx  = tid & 15;       // n-group (8 cols each)
    const int ty  = tid >> 4;       // m-group (8 rows each)
    const int m0  = blockIdx.y * 128;
    const int n0  = blockIdx.x * 128;

    // A: 128 rows x 16 cols; thread -> row=tid/2, col half=(tid&1)*8
    const int ar = tid >> 1;
    const int ac = (tid & 1) * 8;
    // B: 16 rows x 128 cols; thread -> row=tid/32 (and +8), col=(tid&31)*4
    const int br = tid >> 5;
    const int bc = (tid & 31) * 4;

    const float* Aptr = A + (size_t)(m0 + ar) * K + ac;
    const float* Bp0  = B + (size_t)br * N + n0 + bc;
    const float* Bp1  = B + (size_t)(br + 8) * N + n0 + bc;

    // prefetch first tile
    float4 a0 = *(const float4*)(Aptr);
    float4 a1 = *(const float4*)(Aptr + 4);
    float4 b0 = *(const float4*)(Bp0);
    float4 b1 = *(const float4*)(Bp1);

    float acc[8][8];
#pragma unroll
    for (int i = 0; i < 8; i++)
#pragma unroll
        for (int j = 0; j < 8; j++) acc[i][j] = 0.f;

    for (int k0 = 0; k0 < K; k0 += 16) {
        // commit prefetched tile to smem
        As[ac + 0][ar] = a0.x;  As[ac + 1][ar] = a0.y;
        As[ac + 2][ar] = a0.z;  As[ac + 3][ar] = a0.w;
        As[ac + 4][ar] = a1.x;  As[ac + 5][ar] = a1.y;
        As[ac + 6][ar] = a1.z;  As[ac + 7][ar] = a1.w;
        *(float4*)(&Bs[br][bc])     = b0;
        *(float4*)(&Bs[br + 8][bc]) = b1;
        __syncthreads();

        // prefetch next tile into registers
        if (k0 + 16 < K) {
            a0 = *(const float4*)(Aptr + k0 + 16);
            a1 = *(const float4*)(Aptr + k0 + 20);
            b0 = *(const float4*)(Bp0 + (size_t)(k0 + 16) * N);
            b1 = *(const float4*)(Bp1 + (size_t)(k0 + 16) * N);
        }

#pragma unroll
        for (int k = 0; k < 16; k++) {
            float am[8], bn[8];
            *(float4*)(am)     = *(const float4*)(&As[k][ty * 8]);
            *(float4*)(am + 4) = *(const float4*)(&As[k][ty * 8 + 4]);
            *(float4*)(bn)     = *(const float4*)(&Bs[k][tx * 8]);
            *(float4*)(bn + 4) = *(const float4*)(&Bs[k][tx * 8 + 4]);
#pragma unroll
            for (int i = 0; i < 8; i++)
#pragma unroll
                for (int j = 0; j < 8; j++)
                    acc[i][j] += am[i] * bn[j];
        }
        __syncthreads();
    }

#pragma unroll
    for (int i = 0; i < 8; i++) {
        float* c = C + (size_t)(m0 + ty * 8 + i) * N + n0 + tx * 8;
        *(float4*)(c)     = make_float4(acc[i][0], acc[i][1], acc[i][2], acc[i][3]);
        *(float4*)(c + 4) = make_float4(acc[i][4], acc[i][5], acc[i][6], acc[i][7]);
    }
}

// ---------------------------------------------------------------------------
// RoPE, fp64 trig (validated in R5).  One block per position t.
// ---------------------------------------------------------------------------
__global__ __launch_bounds__(256)
void rope2(float* __restrict__ Q, float* __restrict__ K)
{
    const int t = blockIdx.x;
    for (int p = threadIdx.x; p < 40 * 64; p += blockDim.x) {
        const int h = p >> 6;
        const int j = p & 63;

        const double fj  = pow(10000.0, -(double)j / 64.0);
        const double ang = (double)t * fj;
        const float  c   = (float)cos(ang);
        const float  s   = (float)sin(ang);

        float* row;
        if (h < N_HEADS) row = Q + (size_t)t * D_MODEL + h * HD;
        else             row = K + (size_t)t * KV_DIM + (h - N_HEADS) * HD;

        const float v0 = row[j];
        const float v1 = row[j + 64];
        row[j]      = v0 * c - v1 * s;
        row[j + 64] = v1 * c + v0 * s;
    }
}

// ---------------------------------------------------------------------------
// Flash attention, fp32, causal, GQA (R1 implementation; numerically equal
// to the validated naive attention).  BQ=BK=64, 256 threads.
// ---------------------------------------------------------------------------
#define BQ   64
#define BK   64
#define HDP  132

__global__ __launch_bounds__(256)
void flash_attn(const float* __restrict__ Q, const float* __restrict__ K,
                const float* __restrict__ V, float* __restrict__ AO)
{
    extern __shared__ float smem[];
    float* Qs = smem;                 // BQ*HDP
    float* Ks = Qs + BQ * HDP;        // BK*HDP
    float* Vs = Ks + BK * HDP;        // BK*HDP
    float* Ps = Vs + BK * HDP;        // BQ*BK

    const int tid = threadIdx.x;
    const int tx  = tid & 15;
    const int ty  = tid >> 4;
    const int qb  = blockIdx.x;
    const int h   = blockIdx.y;
    const int kh  = h >> 2;           // GQA kv head

    {
        const float* Qg = Q + (size_t)(qb * BQ) * D_MODEL + h * HD;
#pragma unroll
        for (int i = 0; i < 8; i++) {
            int f  = tid + i * 256;
            int r  = f >> 5;
            int c4 = (f & 31) * 4;
            float4 v = *(const float4*)(Qg + (size_t)r * D_MODEL + c4);
            v.x *= SCALE; v.y *= SCALE; v.z *= SCALE; v.w *= SCALE;
            *(float4*)(&Qs[r * HDP + c4]) = v;
        }
    }

    float o[4][8];
#pragma unroll
    for (int i = 0; i < 4; i++)
#pragma unroll
        for (int j = 0; j < 8; j++) o[i][j] = 0.f;
    float m_i[4] = {-1e30f, -1e30f, -1e30f, -1e30f};
    float l_i[4] = {0.f, 0.f, 0.f, 0.f};

    for (int jt = 0; jt <= qb; jt++) {
        const int j0 = jt * BK;
        {
            const float* Kg = K + (size_t)j0 * KV_DIM + kh * HD;
            const float* Vg = V + (size_t)j0 * KV_DIM + kh * HD;
#pragma unroll
            for (int i = 0; i < 8; i++) {
                int f  = tid + i * 256;
                int r  = f >> 5;
                int c4 = (f & 31) * 4;
                *(float4*)(&Ks[r * HDP + c4]) =
                    *(const float4*)(Kg + (size_t)r * KV_DIM + c4);
                *(float4*)(&Vs[r * HDP + c4]) =
                    *(const float4*)(Vg + (size_t)r * KV_DIM + c4);
            }
        }
        __syncthreads();

        float s[4][4];
#pragma unroll
        for (int i = 0; i < 4; i++)
#pragma unroll
            for (int j = 0; j < 4; j++) s[i][j] = 0.f;

#pragma unroll 4
        for (int d = 0; d < HD; d++) {
            float qr[4], kr[4];
#pragma unroll
            for (int i = 0; i < 4; i++) qr[i] = Qs[(ty + i * 16) * HDP + d];
#pragma unroll
            for (int j = 0; j < 4; j++) kr[j] = Ks[(tx + j * 16) * HDP + d];
#pragma unroll
            for (int i = 0; i < 4; i++)
#pragma unroll
                for (int j = 0; j < 4; j++)
                    s[i][j] += qr[i] * kr[j];
        }

        if (jt == qb) {
#pragma unroll
            for (int i = 0; i < 4; i++) {
                int qg = qb * BQ + ty + i * 16;
#pragma unroll
                for (int j = 0; j < 4; j++) {
                    int kg = j0 + tx + j * 16;
                    if (kg > qg) s[i][j] = -1e30f;
                }
            }
        }

#pragma unroll
        for (int i = 0; i < 4; i++) {
            float mx = fmaxf(fmaxf(s[i][0], s[i][1]), fmaxf(s[i][2], s[i][3]));
#pragma unroll
            for (int off = 8; off > 0; off >>= 1)
                mx = fmaxf(mx, __shfl_xor_sync(0xffffffffu, mx, off));
            float mnew  = fmaxf(m_i[i], mx);
            float alpha = __expf(m_i[i] - mnew);
            float rs = 0.f;
#pragma unroll
            for (int j = 0; j < 4; j++) {
                float p = __expf(s[i][j] - mnew);
                s[i][j] = p;
                rs += p;
            }
#pragma unroll
            for (int off = 8; off > 0; off >>= 1)
                rs += __shfl_xor_sync(0xffffffffu, rs, off);
            l_i[i] = l_i[i] * alpha + rs;
            m_i[i] = mnew;
#pragma unroll
            for (int j = 0; j < 8; j++) o[i][j] *= alpha;
        }

#pragma unroll
        for (int i = 0; i < 4; i++)
#pragma unroll
            for (int j = 0; j < 4; j++)
                Ps[(ty + i * 16) * BK + tx + j * 16] = s[i][j];
        __syncthreads();

#pragma unroll 4
        for (int k = 0; k < BK; k++) {
            float pr[4];
#pragma unroll
            for (int i = 0; i < 4; i++) pr[i] = Ps[(ty + i * 16) * BK + k];
            float4 v0 = *(float4*)(&Vs[k * HDP + tx * 8]);
            float4 v1 = *(float4*)(&Vs[k * HDP + tx * 8 + 4]);
            float vr[8] = {v0.x, v0.y, v0.z, v0.w, v1.x, v1.y, v1.z, v1.w};
#pragma unroll
            for (int i = 0; i < 4; i++)
#pragma unroll
                for (int j = 0; j < 8; j++)
                    o[i][j] += pr[i] * vr[j];
        }
        __syncthreads();
    }

    float* Og = AO + (size_t)(qb * BQ) * D_MODEL + h * HD;
#pragma unroll
    for (int i = 0; i < 4; i++) {
        int q = ty + i * 16;
        float inv_l = 1.0f / l_i[i];
        float4 w0 = make_float4(o[i][0] * inv_l, o[i][1] * inv_l,
                                o[i][2] * inv_l, o[i][3] * inv_l);
        float4 w1 = make_float4(o[i][4] * inv_l, o[i][5] * inv_l,
                                o[i][6] * inv_l, o[i][7] * inv_l);
        *(float4*)(Og + (size_t)q * D_MODEL + tx * 8)     = w0;
        *(float4*)(Og + (size_t)q * D_MODEL + tx * 8 + 4) = w1;
    }
}

// ---------------------------------------------------------------------------
// launch — signature order: x, wq, wk, wv, wo
// ---------------------------------------------------------------------------
extern "C" void kernel_launch(void* const* d_in, const int* in_sizes, int n_in,
                              void* d_out, int out_size)
{
    const float* x  = (const float*)d_in[0];
    const float* wq = (const float*)d_in[1];
    const float* wk = (const float*)d_in[2];
    const float* wv = (const float*)d_in[3];
    const float* wo = (const float*)d_in[4];
    float* out = (float*)d_out;

    float *Qp, *Kp, *Vp, *Ap;
    cudaGetSymbolAddress((void**)&Qp, g_Q);
    cudaGetSymbolAddress((void**)&Kp, g_K);
    cudaGetSymbolAddress((void**)&Vp, g_V);
    cudaGetSymbolAddress((void**)&Ap, g_AO);

    const int smem_flash = (BQ * HDP + 2 * BK * HDP + BQ * BK) * (int)sizeof(float);
    cudaFuncSetAttribute(flash_attn, cudaFuncAttributeMaxDynamicSharedMemorySize,
                         smem_flash);

    // projections (tiled SGEMM)
    sgemm_t<<<dim3(D_MODEL / 128, T_SEQ / 128), 256>>>(x, wq, Qp, T_SEQ, D_MODEL, D_MODEL);
    sgemm_t<<<dim3(KV_DIM / 128, T_SEQ / 128), 256>>>(x, wk, Kp, T_SEQ, KV_DIM, D_MODEL);
    sgemm_t<<<dim3(KV_DIM / 128, T_SEQ / 128), 256>>>(x, wv, Vp, T_SEQ, KV_DIM, D_MODEL);

    // RoPE
    rope2<<<T_SEQ, 256>>>(Qp, Kp);

    // attention (flash)
    flash_attn<<<dim3(T_SEQ / BQ, N_HEADS), 256, smem_flash>>>(Qp, Kp, Vp, Ap);

    // output projection
    sgemm_t<<<dim3(D_MODEL / 128, T_SEQ / 128), 256>>>(Ap, wo, out, T_SEQ, D_MODEL, D_MODEL);
}

// round 7
// speedup vs baseline: 8.1796x; 2.4631x over previous
#include <cuda_runtime.h>
#include <cuda_bf16.h>
#include <math.h>
#include <stdint.h>

// ---------------------------------------------------------------------------
// LLaMA attention block.
//   x:[2048,4096] wq:[4096,4096] wk,wv:[4096,1024] wo:[4096,4096]
// GEMMs: bf16x2 split-precision tensor-core MMA (AhBh + AhBl + AlBh, fp32 acc)
// Attention: fp32 flash (validated).  RoPE: fp64 trig (validated).
// ---------------------------------------------------------------------------

#define T_SEQ   2048
#define D_MODEL 4096
#define KV_DIM  1024
#define N_HEADS 32
#define HD      128
#define SCALE   0.08838834764831845f   // 1/sqrt(128)

#define SZ_X    (T_SEQ * D_MODEL)
#define SZ_WQ   (D_MODEL * D_MODEL)
#define SZ_WK   (D_MODEL * KV_DIM)

// fp32 scratch
__device__ float g_Q [T_SEQ * D_MODEL];
__device__ float g_K [T_SEQ * KV_DIM];
__device__ float g_V [T_SEQ * KV_DIM];
__device__ float g_AO[T_SEQ * D_MODEL];
// bf16 hi/lo scratch (weights stored TRANSPOSED: [N][K])
__device__ __nv_bfloat16 g_xh [SZ_X],  g_xl [SZ_X];
__device__ __nv_bfloat16 g_aoh[SZ_X],  g_aol[SZ_X];
__device__ __nv_bfloat16 g_wqh[SZ_WQ], g_wql[SZ_WQ];
__device__ __nv_bfloat16 g_wkh[SZ_WK], g_wkl[SZ_WK];
__device__ __nv_bfloat16 g_wvh[SZ_WK], g_wvl[SZ_WK];
__device__ __nv_bfloat16 g_woh[SZ_WQ], g_wol[SZ_WQ];

// ---------------------------------------------------------------------------
// helpers
// ---------------------------------------------------------------------------
__device__ __forceinline__ uint32_t s2u(const void* p) {
    return (uint32_t)__cvta_generic_to_shared(p);
}
__device__ __forceinline__ void ldmx4(uint32_t& r0, uint32_t& r1,
                                      uint32_t& r2, uint32_t& r3, uint32_t a) {
    asm volatile("ldmatrix.sync.aligned.m8n8.x4.shared.b16 {%0,%1,%2,%3},[%4];\n"
                 : "=r"(r0), "=r"(r1), "=r"(r2), "=r"(r3) : "r"(a));
}
__device__ __forceinline__ void mma_bf16(float* d, const uint32_t* a,
                                         const uint32_t* b) {
    asm volatile(
        "mma.sync.aligned.m16n8k16.row.col.f32.bf16.bf16.f32 "
        "{%0,%1,%2,%3},{%4,%5,%6,%7},{%8,%9},{%0,%1,%2,%3};\n"
        : "+f"(d[0]), "+f"(d[1]), "+f"(d[2]), "+f"(d[3])
        : "r"(a[0]), "r"(a[1]), "r"(a[2]), "r"(a[3]), "r"(b[0]), "r"(b[1]));
}
__device__ __forceinline__ void split_hl(float v, __nv_bfloat16& h, __nv_bfloat16& l) {
    h = __float2bfloat16(v);
    l = __float2bfloat16(v - __bfloat162float(h));
}

// ---------------------------------------------------------------------------
// conversion: fp32 [n] -> bf16 hi/lo (row-major preserved)
// ---------------------------------------------------------------------------
__global__ __launch_bounds__(256)
void conv_hilo(const float* __restrict__ s, __nv_bfloat16* __restrict__ h,
               __nv_bfloat16* __restrict__ l, int n)
{
    int i = (blockIdx.x * blockDim.x + threadIdx.x) * 4;
    if (i >= n) return;
    float4 v = *(const float4*)(s + i);
    __nv_bfloat16 hh[4], ll[4];
    split_hl(v.x, hh[0], ll[0]);
    split_hl(v.y, hh[1], ll[1]);
    split_hl(v.z, hh[2], ll[2]);
    split_hl(v.w, hh[3], ll[3]);
    *(uint2*)(h + i) = *(uint2*)hh;
    *(uint2*)(l + i) = *(uint2*)ll;
}

// ---------------------------------------------------------------------------
// conversion + transpose: W [K,N] fp32 -> Wt hi/lo [N,K] bf16
// ---------------------------------------------------------------------------
__global__ __launch_bounds__(256)
void conv_t(const float* __restrict__ w, __nv_bfloat16* __restrict__ th,
            __nv_bfloat16* __restrict__ tl, int K, int N)
{
    __shared__ float tile[32][33];
    const int n0 = blockIdx.x * 32, k0 = blockIdx.y * 32;
    const int tx = threadIdx.x, ty = threadIdx.y;   // 32 x 8
#pragma unroll
    for (int i = 0; i < 4; i++)
        tile[ty + 8 * i][tx] = w[(size_t)(k0 + ty + 8 * i) * N + n0 + tx];
    __syncthreads();
#pragma unroll
    for (int i = 0; i < 4; i++) {
        float v = tile[tx][ty + 8 * i];        // = w[k0+tx][n0+ty+8i]
        __nv_bfloat16 h, l;
        split_hl(v, h, l);
        size_t o = (size_t)(n0 + ty + 8 * i) * K + k0 + tx;
        th[o] = h;
        tl[o] = l;
    }
}

// ---------------------------------------------------------------------------
// bf16x2-split MMA GEMM: C[M,N] = A[M,K] * B^T  where Bt is stored [N][K].
// BM=BN=128, BK=32, 256 thr (8 warps, 2m x 4n), warp tile 64x32.
// ---------------------------------------------------------------------------
#define SST 40   // smem row stride (elems): conflict-free for ldmatrix

__global__ __launch_bounds__(256)
void gemm_bf16x2(const __nv_bfloat16* __restrict__ Ah, const __nv_bfloat16* __restrict__ Al,
                 const __nv_bfloat16* __restrict__ Bh, const __nv_bfloat16* __restrict__ Bl,
                 float* __restrict__ C, int M, int N, int K)
{
    __shared__ __nv_bfloat16 sAh[128][SST], sAl[128][SST];
    __shared__ __nv_bfloat16 sBh[128][SST], sBl[128][SST];

    const int tid  = threadIdx.x;
    const int lane = tid & 31;
    const int wid  = tid >> 5;
    const int m0 = blockIdx.y * 128, n0 = blockIdx.x * 128;
    const int wm = (wid & 1) * 64;      // warp m offset
    const int wn = (wid >> 1) * 32;     // warp n offset

    // global->smem mapping: 128 rows x 32 cols bf16, uint4 = 8 elems
    const int lr = tid >> 2;            // 0..63
    const int lk = (tid & 3) * 8;       // 0,8,16,24

    float acc[4][4][4];
#pragma unroll
    for (int a = 0; a < 4; a++)
#pragma unroll
        for (int b = 0; b < 4; b++)
#pragma unroll
            for (int c = 0; c < 4; c++) acc[a][b][c] = 0.f;

    // ldmatrix source addresses (per-thread, fixed row/col pattern)
    const int a_row = ((lane >> 3) & 1) * 8 + (lane & 7);
    const int a_col = (lane >> 4) * 8;
    const int b_row = ((lane >> 4) & 1) * 8 + (lane & 7);
    const int b_col = ((lane >> 3) & 1) * 8;

    for (int k0 = 0; k0 < K; k0 += 32) {
        const __nv_bfloat16* pa = Ah + (size_t)(m0 + lr) * K + k0 + lk;
        const __nv_bfloat16* pb = Bh + (size_t)(n0 + lr) * K + k0 + lk;
        const __nv_bfloat16* qa = Al + (size_t)(m0 + lr) * K + k0 + lk;
        const __nv_bfloat16* qb = Bl + (size_t)(n0 + lr) * K + k0 + lk;
        *(uint4*)&sAh[lr     ][lk] = *(const uint4*)(pa);
        *(uint4*)&sAh[lr + 64][lk] = *(const uint4*)(pa + (size_t)64 * K);
        *(uint4*)&sAl[lr     ][lk] = *(const uint4*)(qa);
        *(uint4*)&sAl[lr + 64][lk] = *(const uint4*)(qa + (size_t)64 * K);
        *(uint4*)&sBh[lr     ][lk] = *(const uint4*)(pb);
        *(uint4*)&sBh[lr + 64][lk] = *(const uint4*)(pb + (size_t)64 * K);
        *(uint4*)&sBl[lr     ][lk] = *(const uint4*)(qb);
        *(uint4*)&sBl[lr + 64][lk] = *(const uint4*)(qb + (size_t)64 * K);
        __syncthreads();

#pragma unroll
        for (int kk = 0; kk < 32; kk += 16) {
            uint32_t ah[4][4], al[4][4], bh[4][2], bl[4][2];
#pragma unroll
            for (int mi = 0; mi < 4; mi++) {
                ldmx4(ah[mi][0], ah[mi][1], ah[mi][2], ah[mi][3],
                      s2u(&sAh[wm + 16 * mi + a_row][kk + a_col]));
                ldmx4(al[mi][0], al[mi][1], al[mi][2], al[mi][3],
                      s2u(&sAl[wm + 16 * mi + a_row][kk + a_col]));
            }
#pragma unroll
            for (int nj = 0; nj < 2; nj++) {
                uint32_t t0, t1, t2, t3;
                ldmx4(t0, t1, t2, t3,
                      s2u(&sBh[wn + 16 * nj + b_row][kk + b_col]));
                bh[2 * nj][0] = t0; bh[2 * nj][1] = t1;
                bh[2 * nj + 1][0] = t2; bh[2 * nj + 1][1] = t3;
                ldmx4(t0, t1, t2, t3,
                      s2u(&sBl[wn + 16 * nj + b_row][kk + b_col]));
                bl[2 * nj][0] = t0; bl[2 * nj][1] = t1;
                bl[2 * nj + 1][0] = t2; bl[2 * nj + 1][1] = t3;
            }
#pragma unroll
            for (int mi = 0; mi < 4; mi++)
#pragma unroll
                for (int ni = 0; ni < 4; ni++) {
                    mma_bf16(acc[mi][ni], ah[mi], bh[ni]);
                    mma_bf16(acc[mi][ni], ah[mi], bl[ni]);
                    mma_bf16(acc[mi][ni], al[mi], bh[ni]);
                }
        }
        __syncthreads();
    }

    // store C
    const int g  = lane >> 2;
    const int t2 = (lane & 3) * 2;
#pragma unroll
    for (int mi = 0; mi < 4; mi++)
#pragma unroll
        for (int ni = 0; ni < 4; ni++) {
            const int row = m0 + wm + 16 * mi + g;
            const int col = n0 + wn + 8 * ni + t2;
            *(float2*)&C[(size_t)row * N + col] =
                make_float2(acc[mi][ni][0], acc[mi][ni][1]);
            *(float2*)&C[(size_t)(row + 8) * N + col] =
                make_float2(acc[mi][ni][2], acc[mi][ni][3]);
        }
}

// ---------------------------------------------------------------------------
// RoPE, fp64 trig (validated).
// ---------------------------------------------------------------------------
__global__ __launch_bounds__(256)
void rope2(float* __restrict__ Q, float* __restrict__ K)
{
    const int t = blockIdx.x;
    for (int p = threadIdx.x; p < 40 * 64; p += blockDim.x) {
        const int h = p >> 6;
        const int j = p & 63;
        const double fj  = pow(10000.0, -(double)j / 64.0);
        const double ang = (double)t * fj;
        const float  c   = (float)cos(ang);
        const float  s   = (float)sin(ang);
        float* row;
        if (h < N_HEADS) row = Q + (size_t)t * D_MODEL + h * HD;
        else             row = K + (size_t)t * KV_DIM + (h - N_HEADS) * HD;
        const float v0 = row[j];
        const float v1 = row[j + 64];
        row[j]      = v0 * c - v1 * s;
        row[j + 64] = v1 * c + v0 * s;
    }
}

// ---------------------------------------------------------------------------
// Flash attention, fp32, causal, GQA (validated).  BQ=BK=64, 256 threads.
// ---------------------------------------------------------------------------
#define BQ   64
#define BK   64
#define HDP  132

__global__ __launch_bounds__(256)
void flash_attn(const float* __restrict__ Q, const float* __restrict__ K,
                const float* __restrict__ V, float* __restrict__ AO)
{
    extern __shared__ float smem[];
    float* Qs = smem;
    float* Ks = Qs + BQ * HDP;
    float* Vs = Ks + BK * HDP;
    float* Ps = Vs + BK * HDP;

    const int tid = threadIdx.x;
    const int tx  = tid & 15;
    const int ty  = tid >> 4;
    const int qb  = blockIdx.x;
    const int h   = blockIdx.y;
    const int kh  = h >> 2;

    {
        const float* Qg = Q + (size_t)(qb * BQ) * D_MODEL + h * HD;
#pragma unroll
        for (int i = 0; i < 8; i++) {
            int f = tid + i * 256, r = f >> 5, c4 = (f & 31) * 4;
            float4 v = *(const float4*)(Qg + (size_t)r * D_MODEL + c4);
            v.x *= SCALE; v.y *= SCALE; v.z *= SCALE; v.w *= SCALE;
            *(float4*)(&Qs[r * HDP + c4]) = v;
        }
    }

    float o[4][8];
#pragma unroll
    for (int i = 0; i < 4; i++)
#pragma unroll
        for (int j = 0; j < 8; j++) o[i][j] = 0.f;
    float m_i[4] = {-1e30f, -1e30f, -1e30f, -1e30f};
    float l_i[4] = {0.f, 0.f, 0.f, 0.f};

    for (int jt = 0; jt <= qb; jt++) {
        const int j0 = jt * BK;
        {
            const float* Kg = K + (size_t)j0 * KV_DIM + kh * HD;
            const float* Vg = V + (size_t)j0 * KV_DIM + kh * HD;
#pragma unroll
            for (int i = 0; i < 8; i++) {
                int f = tid + i * 256, r = f >> 5, c4 = (f & 31) * 4;
                *(float4*)(&Ks[r * HDP + c4]) =
                    *(const float4*)(Kg + (size_t)r * KV_DIM + c4);
                *(float4*)(&Vs[r * HDP + c4]) =
                    *(const float4*)(Vg + (size_t)r * KV_DIM + c4);
            }
        }
        __syncthreads();

        float s[4][4];
#pragma unroll
        for (int i = 0; i < 4; i++)
#pragma unroll
            for (int j = 0; j < 4; j++) s[i][j] = 0.f;

#pragma unroll 4
        for (int d = 0; d < HD; d++) {
            float qr[4], kr[4];
#pragma unroll
            for (int i = 0; i < 4; i++) qr[i] = Qs[(ty + i * 16) * HDP + d];
#pragma unroll
            for (int j = 0; j < 4; j++) kr[j] = Ks[(tx + j * 16) * HDP + d];
#pragma unroll
            for (int i = 0; i < 4; i++)
#pragma unroll
                for (int j = 0; j < 4; j++)
                    s[i][j] += qr[i] * kr[j];
        }

        if (jt == qb) {
#pragma unroll
            for (int i = 0; i < 4; i++) {
                int qg = qb * BQ + ty + i * 16;
#pragma unroll
                for (int j = 0; j < 4; j++)
                    if (j0 + tx + j * 16 > qg) s[i][j] = -1e30f;
            }
        }

#pragma unroll
        for (int i = 0; i < 4; i++) {
            float mx = fmaxf(fmaxf(s[i][0], s[i][1]), fmaxf(s[i][2], s[i][3]));
#pragma unroll
            for (int off = 8; off > 0; off >>= 1)
                mx = fmaxf(mx, __shfl_xor_sync(0xffffffffu, mx, off));
            float mnew  = fmaxf(m_i[i], mx);
            float alpha = __expf(m_i[i] - mnew);
            float rs = 0.f;
#pragma unroll
            for (int j = 0; j < 4; j++) {
                float p = __expf(s[i][j] - mnew);
                s[i][j] = p;
                rs += p;
            }
#pragma unroll
            for (int off = 8; off > 0; off >>= 1)
                rs += __shfl_xor_sync(0xffffffffu, rs, off);
            l_i[i] = l_i[i] * alpha + rs;
            m_i[i] = mnew;
#pragma unroll
            for (int j = 0; j < 8; j++) o[i][j] *= alpha;
        }

#pragma unroll
        for (int i = 0; i < 4; i++)
#pragma unroll
            for (int j = 0; j < 4; j++)
                Ps[(ty + i * 16) * BK + tx + j * 16] = s[i][j];
        __syncthreads();

#pragma unroll 4
        for (int k = 0; k < BK; k++) {
            float pr[4];
#pragma unroll
            for (int i = 0; i < 4; i++) pr[i] = Ps[(ty + i * 16) * BK + k];
            float4 v0 = *(float4*)(&Vs[k * HDP + tx * 8]);
            float4 v1 = *(float4*)(&Vs[k * HDP + tx * 8 + 4]);
            float vr[8] = {v0.x, v0.y, v0.z, v0.w, v1.x, v1.y, v1.z, v1.w};
#pragma unroll
            for (int i = 0; i < 4; i++)
#pragma unroll
                for (int j = 0; j < 8; j++)
                    o[i][j] += pr[i] * vr[j];
        }
        __syncthreads();
    }

    float* Og = AO + (size_t)(qb * BQ) * D_MODEL + h * HD;
#pragma unroll
    for (int i = 0; i < 4; i++) {
        int q = ty + i * 16;
        float inv_l = 1.0f / l_i[i];
        float4 w0 = make_float4(o[i][0] * inv_l, o[i][1] * inv_l,
                                o[i][2] * inv_l, o[i][3] * inv_l);
        float4 w1 = make_float4(o[i][4] * inv_l, o[i][5] * inv_l,
                                o[i][6] * inv_l, o[i][7] * inv_l);
        *(float4*)(Og + (size_t)q * D_MODEL + tx * 8)     = w0;
        *(float4*)(Og + (size_t)q * D_MODEL + tx * 8 + 4) = w1;
    }
}

// ---------------------------------------------------------------------------
// launch — signature order: x, wq, wk, wv, wo
// ---------------------------------------------------------------------------
extern "C" void kernel_launch(void* const* d_in, const int* in_sizes, int n_in,
                              void* d_out, int out_size)
{
    const float* x  = (const float*)d_in[0];
    const float* wq = (const float*)d_in[1];
    const float* wk = (const float*)d_in[2];
    const float* wv = (const float*)d_in[3];
    const float* wo = (const float*)d_in[4];
    float* out = (float*)d_out;

    float *Qp, *Kp, *Vp, *Ap;
    __nv_bfloat16 *xh, *xl, *aoh, *aol, *wqh, *wql, *wkh, *wkl, *wvh, *wvl, *woh, *wol;
    cudaGetSymbolAddress((void**)&Qp,  g_Q);
    cudaGetSymbolAddress((void**)&Kp,  g_K);
    cudaGetSymbolAddress((void**)&Vp,  g_V);
    cudaGetSymbolAddress((void**)&Ap,  g_AO);
    cudaGetSymbolAddress((void**)&xh,  g_xh);  cudaGetSymbolAddress((void**)&xl,  g_xl);
    cudaGetSymbolAddress((void**)&aoh, g_aoh); cudaGetSymbolAddress((void**)&aol, g_aol);
    cudaGetSymbolAddress((void**)&wqh, g_wqh); cudaGetSymbolAddress((void**)&wql, g_wql);
    cudaGetSymbolAddress((void**)&wkh, g_wkh); cudaGetSymbolAddress((void**)&wkl, g_wkl);
    cudaGetSymbolAddress((void**)&wvh, g_wvh); cudaGetSymbolAddress((void**)&wvl, g_wvl);
    cudaGetSymbolAddress((void**)&woh, g_woh); cudaGetSymbolAddress((void**)&wol, g_wol);

    const int smem_flash = (BQ * HDP + 2 * BK * HDP + BQ * BK) * (int)sizeof(float);
    cudaFuncSetAttribute(flash_attn, cudaFuncAttributeMaxDynamicSharedMemorySize,
                         smem_flash);

    // conversions
    conv_hilo<<<SZ_X / (256 * 4), 256>>>(x, xh, xl, SZ_X);
    conv_t<<<dim3(D_MODEL / 32, D_MODEL / 32), dim3(32, 8)>>>(wq, wqh, wql, D_MODEL, D_MODEL);
    conv_t<<<dim3(KV_DIM / 32, D_MODEL / 32), dim3(32, 8)>>>(wk, wkh, wkl, D_MODEL, KV_DIM);
    conv_t<<<dim3(KV_DIM / 32, D_MODEL / 32), dim3(32, 8)>>>(wv, wvh, wvl, D_MODEL, KV_DIM);
    conv_t<<<dim3(D_MODEL / 32, D_MODEL / 32), dim3(32, 8)>>>(wo, woh, wol, D_MODEL, D_MODEL);

    // projections (tensor cores)
    gemm_bf16x2<<<dim3(D_MODEL / 128, T_SEQ / 128), 256>>>(xh, xl, wqh, wql, Qp, T_SEQ, D_MODEL, D_MODEL);
    gemm_bf16x2<<<dim3(KV_DIM / 128, T_SEQ / 128), 256>>>(xh, xl, wkh, wkl, Kp, T_SEQ, KV_DIM, D_MODEL);
    gemm_bf16x2<<<dim3(KV_DIM / 128, T_SEQ / 128), 256>>>(xh, xl, wvh, wvl, Vp, T_SEQ, KV_DIM, D_MODEL);

    // RoPE
    rope2<<<T_SEQ, 256>>>(Qp, Kp);

    // attention
    flash_attn<<<dim3(T_SEQ / BQ, N_HEADS), 256, smem_flash>>>(Qp, Kp, Vp, Ap);

    // output projection
    conv_hilo<<<SZ_X / (256 * 4), 256>>>(Ap, aoh, aol, SZ_X);
    gemm_bf16x2<<<dim3(D_MODEL / 128, T_SEQ / 128), 256>>>(aoh, aol, woh, wol, out, T_SEQ, D_MODEL, D_MODEL);
}

// round 8
// speedup vs baseline: 9.4746x; 1.1583x over previous
#include <cuda_runtime.h>
#include <cuda_bf16.h>
#include <math.h>
#include <stdint.h>

// ---------------------------------------------------------------------------
// LLaMA attention block.
// GEMMs: bf16x2 split tensor-core MMA.  Attention: bf16x2 split FA2 (tensor).
// RoPE: fp64 trig.  All validated pieces retained from R7.
// ---------------------------------------------------------------------------

#define T_SEQ   2048
#define D_MODEL 4096
#define KV_DIM  1024
#define N_HEADS 32
#define HD      128
#define SCALE   0.08838834764831845f   // 1/sqrt(128)

#define SZ_X    (T_SEQ * D_MODEL)
#define SZ_WQ   (D_MODEL * D_MODEL)
#define SZ_WK   (D_MODEL * KV_DIM)
#define SZ_KV   (T_SEQ * KV_DIM)

// fp32 scratch
__device__ float g_Q [SZ_X];
__device__ float g_K [SZ_KV];
__device__ float g_V [SZ_KV];
__device__ float g_AO[SZ_X];
// bf16 hi/lo scratch (weights TRANSPOSED: [N][K])
__device__ __nv_bfloat16 g_xh [SZ_X],  g_xl [SZ_X];
__device__ __nv_bfloat16 g_aoh[SZ_X],  g_aol[SZ_X];
__device__ __nv_bfloat16 g_wqh[SZ_WQ], g_wql[SZ_WQ];
__device__ __nv_bfloat16 g_wkh[SZ_WK], g_wkl[SZ_WK];
__device__ __nv_bfloat16 g_wvh[SZ_WK], g_wvl[SZ_WK];
__device__ __nv_bfloat16 g_woh[SZ_WQ], g_wol[SZ_WQ];
// attention operands, hi/lo
__device__ __nv_bfloat16 g_Qh[SZ_X],  g_Ql[SZ_X];
__device__ __nv_bfloat16 g_Kh[SZ_KV], g_Kl[SZ_KV];
__device__ __nv_bfloat16 g_Vh[SZ_KV], g_Vl[SZ_KV];

// ---------------------------------------------------------------------------
// helpers
// ---------------------------------------------------------------------------
__device__ __forceinline__ uint32_t s2u(const void* p) {
    return (uint32_t)__cvta_generic_to_shared(p);
}
__device__ __forceinline__ void ldmx4(uint32_t& r0, uint32_t& r1,
                                      uint32_t& r2, uint32_t& r3, uint32_t a) {
    asm volatile("ldmatrix.sync.aligned.m8n8.x4.shared.b16 {%0,%1,%2,%3},[%4];\n"
                 : "=r"(r0), "=r"(r1), "=r"(r2), "=r"(r3) : "r"(a));
}
__device__ __forceinline__ void ldmx4t(uint32_t& r0, uint32_t& r1,
                                       uint32_t& r2, uint32_t& r3, uint32_t a) {
    asm volatile("ldmatrix.sync.aligned.m8n8.x4.trans.shared.b16 {%0,%1,%2,%3},[%4];\n"
                 : "=r"(r0), "=r"(r1), "=r"(r2), "=r"(r3) : "r"(a));
}
__device__ __forceinline__ void mma16816(float* d, uint32_t a0, uint32_t a1,
                                         uint32_t a2, uint32_t a3,
                                         uint32_t b0, uint32_t b1) {
    asm volatile(
        "mma.sync.aligned.m16n8k16.row.col.f32.bf16.bf16.f32 "
        "{%0,%1,%2,%3},{%4,%5,%6,%7},{%8,%9},{%0,%1,%2,%3};\n"
        : "+f"(d[0]), "+f"(d[1]), "+f"(d[2]), "+f"(d[3])
        : "r"(a0), "r"(a1), "r"(a2), "r"(a3), "r"(b0), "r"(b1));
}
__device__ __forceinline__ void split_hl(float v, __nv_bfloat16& h, __nv_bfloat16& l) {
    h = __float2bfloat16(v);
    l = __float2bfloat16(v - __bfloat162float(h));
}
// pack two fp32 -> bf16x2 hi reg, with lo reg out-param
__device__ __forceinline__ uint32_t pack_hl(float a, float b, uint32_t& lo) {
    __nv_bfloat16 ha, la, hb, lb;
    split_hl(a, ha, la);
    split_hl(b, hb, lb);
    __nv_bfloat162 H; H.x = ha; H.y = hb;
    __nv_bfloat162 L; L.x = la; L.y = lb;
    lo = *(uint32_t*)&L;
    return *(uint32_t*)&H;
}

// ---------------------------------------------------------------------------
// fp32 -> bf16 hi/lo (optionally scaled)
// ---------------------------------------------------------------------------
__global__ __launch_bounds__(256)
void conv_hilo(const float* __restrict__ s, __nv_bfloat16* __restrict__ h,
               __nv_bfloat16* __restrict__ l, int n, float scale)
{
    int i = (blockIdx.x * blockDim.x + threadIdx.x) * 4;
    if (i >= n) return;
    float4 v = *(const float4*)(s + i);
    __nv_bfloat16 hh[4], ll[4];
    split_hl(v.x * scale, hh[0], ll[0]);
    split_hl(v.y * scale, hh[1], ll[1]);
    split_hl(v.z * scale, hh[2], ll[2]);
    split_hl(v.w * scale, hh[3], ll[3]);
    *(uint2*)(h + i) = *(uint2*)hh;
    *(uint2*)(l + i) = *(uint2*)ll;
}

// ---------------------------------------------------------------------------
// conversion + transpose: W [K,N] fp32 -> Wt hi/lo [N,K] bf16
// ---------------------------------------------------------------------------
__global__ __launch_bounds__(256)
void conv_t(const float* __restrict__ w, __nv_bfloat16* __restrict__ th,
            __nv_bfloat16* __restrict__ tl, int K, int N)
{
    __shared__ float tile[32][33];
    const int n0 = blockIdx.x * 32, k0 = blockIdx.y * 32;
    const int tx = threadIdx.x, ty = threadIdx.y;
#pragma unroll
    for (int i = 0; i < 4; i++)
        tile[ty + 8 * i][tx] = w[(size_t)(k0 + ty + 8 * i) * N + n0 + tx];
    __syncthreads();
#pragma unroll
    for (int i = 0; i < 4; i++) {
        float v = tile[tx][ty + 8 * i];
        __nv_bfloat16 h, l;
        split_hl(v, h, l);
        size_t o = (size_t)(n0 + ty + 8 * i) * K + k0 + tx;
        th[o] = h;
        tl[o] = l;
    }
}

// ---------------------------------------------------------------------------
// bf16x2-split MMA GEMM (validated R7): C = A * Bt^T, Bt stored [N][K].
// ---------------------------------------------------------------------------
#define SST 40

__global__ __launch_bounds__(256)
void gemm_bf16x2(const __nv_bfloat16* __restrict__ Ah, const __nv_bfloat16* __restrict__ Al,
                 const __nv_bfloat16* __restrict__ Bh, const __nv_bfloat16* __restrict__ Bl,
                 float* __restrict__ C, int M, int N, int K)
{
    __shared__ __nv_bfloat16 sAh[128][SST], sAl[128][SST];
    __shared__ __nv_bfloat16 sBh[128][SST], sBl[128][SST];

    const int tid  = threadIdx.x;
    const int lane = tid & 31;
    const int wid  = tid >> 5;
    const int m0 = blockIdx.y * 128, n0 = blockIdx.x * 128;
    const int wm = (wid & 1) * 64;
    const int wn = (wid >> 1) * 32;

    const int lr = tid >> 2;
    const int lk = (tid & 3) * 8;

    float acc[4][4][4];
#pragma unroll
    for (int a = 0; a < 4; a++)
#pragma unroll
        for (int b = 0; b < 4; b++)
#pragma unroll
            for (int c = 0; c < 4; c++) acc[a][b][c] = 0.f;

    const int a_row = ((lane >> 3) & 1) * 8 + (lane & 7);
    const int a_col = (lane >> 4) * 8;
    const int b_row = ((lane >> 4) & 1) * 8 + (lane & 7);
    const int b_col = ((lane >> 3) & 1) * 8;

    for (int k0 = 0; k0 < K; k0 += 32) {
        const __nv_bfloat16* pa = Ah + (size_t)(m0 + lr) * K + k0 + lk;
        const __nv_bfloat16* pb = Bh + (size_t)(n0 + lr) * K + k0 + lk;
        const __nv_bfloat16* qa = Al + (size_t)(m0 + lr) * K + k0 + lk;
        const __nv_bfloat16* qb = Bl + (size_t)(n0 + lr) * K + k0 + lk;
        *(uint4*)&sAh[lr     ][lk] = *(const uint4*)(pa);
        *(uint4*)&sAh[lr + 64][lk] = *(const uint4*)(pa + (size_t)64 * K);
        *(uint4*)&sAl[lr     ][lk] = *(const uint4*)(qa);
        *(uint4*)&sAl[lr + 64][lk] = *(const uint4*)(qa + (size_t)64 * K);
        *(uint4*)&sBh[lr     ][lk] = *(const uint4*)(pb);
        *(uint4*)&sBh[lr + 64][lk] = *(const uint4*)(pb + (size_t)64 * K);
        *(uint4*)&sBl[lr     ][lk] = *(const uint4*)(qb);
        *(uint4*)&sBl[lr + 64][lk] = *(const uint4*)(qb + (size_t)64 * K);
        __syncthreads();

#pragma unroll
        for (int kk = 0; kk < 32; kk += 16) {
            uint32_t ah[4][4], al[4][4], bh[4][2], bl[4][2];
#pragma unroll
            for (int mi = 0; mi < 4; mi++) {
                ldmx4(ah[mi][0], ah[mi][1], ah[mi][2], ah[mi][3],
                      s2u(&sAh[wm + 16 * mi + a_row][kk + a_col]));
                ldmx4(al[mi][0], al[mi][1], al[mi][2], al[mi][3],
                      s2u(&sAl[wm + 16 * mi + a_row][kk + a_col]));
            }
#pragma unroll
            for (int nj = 0; nj < 2; nj++) {
                uint32_t t0, t1, t2, t3;
                ldmx4(t0, t1, t2, t3, s2u(&sBh[wn + 16 * nj + b_row][kk + b_col]));
                bh[2 * nj][0] = t0; bh[2 * nj][1] = t1;
                bh[2 * nj + 1][0] = t2; bh[2 * nj + 1][1] = t3;
                ldmx4(t0, t1, t2, t3, s2u(&sBl[wn + 16 * nj + b_row][kk + b_col]));
                bl[2 * nj][0] = t0; bl[2 * nj][1] = t1;
                bl[2 * nj + 1][0] = t2; bl[2 * nj + 1][1] = t3;
            }
#pragma unroll
            for (int mi = 0; mi < 4; mi++)
#pragma unroll
                for (int ni = 0; ni < 4; ni++) {
                    mma16816(acc[mi][ni], ah[mi][0], ah[mi][1], ah[mi][2], ah[mi][3],
                             bh[ni][0], bh[ni][1]);
                    mma16816(acc[mi][ni], ah[mi][0], ah[mi][1], ah[mi][2], ah[mi][3],
                             bl[ni][0], bl[ni][1]);
                    mma16816(acc[mi][ni], al[mi][0], al[mi][1], al[mi][2], al[mi][3],
                             bh[ni][0], bh[ni][1]);
                }
        }
        __syncthreads();
    }

    const int g  = lane >> 2;
    const int t2 = (lane & 3) * 2;
#pragma unroll
    for (int mi = 0; mi < 4; mi++)
#pragma unroll
        for (int ni = 0; ni < 4; ni++) {
            const int row = m0 + wm + 16 * mi + g;
            const int col = n0 + wn + 8 * ni + t2;
            *(float2*)&C[(size_t)row * N + col] =
                make_float2(acc[mi][ni][0], acc[mi][ni][1]);
            *(float2*)&C[(size_t)(row + 8) * N + col] =
                make_float2(acc[mi][ni][2], acc[mi][ni][3]);
        }
}

// ---------------------------------------------------------------------------
// RoPE, fp64 trig (validated)
// ---------------------------------------------------------------------------
__global__ __launch_bounds__(256)
void rope2(float* __restrict__ Q, float* __restrict__ K)
{
    const int t = blockIdx.x;
    for (int p = threadIdx.x; p < 40 * 64; p += blockDim.x) {
        const int h = p >> 6;
        const int j = p & 63;
        const double fj  = pow(10000.0, -(double)j / 64.0);
        const double ang = (double)t * fj;
        const float  c   = (float)cos(ang);
        const float  s   = (float)sin(ang);
        float* row;
        if (h < N_HEADS) row = Q + (size_t)t * D_MODEL + h * HD;
        else             row = K + (size_t)t * KV_DIM + (h - N_HEADS) * HD;
        const float v0 = row[j];
        const float v1 = row[j + 64];
        row[j]      = v0 * c - v1 * s;
        row[j + 64] = v1 * c + v0 * s;
    }
}

// ---------------------------------------------------------------------------
// Tensor-core flash attention (FA2), bf16x2 split, causal, GQA.
// Block: 128 thr (4 warps x 16 q-rows).  BQ=BK=64.  Smem stride 136 elems.
// ---------------------------------------------------------------------------
#define FST 136   // smem row stride (bf16 elems); 272B => conflict-free ldmatrix
#define FTILE (64 * FST)

__global__ __launch_bounds__(128)
void flash2(const __nv_bfloat16* __restrict__ Qh, const __nv_bfloat16* __restrict__ Ql,
            const __nv_bfloat16* __restrict__ Kh, const __nv_bfloat16* __restrict__ Kl,
            const __nv_bfloat16* __restrict__ Vh, const __nv_bfloat16* __restrict__ Vl,
            float* __restrict__ AO)
{
    extern __shared__ __nv_bfloat16 sm[];
    __nv_bfloat16* sQh = sm;
    __nv_bfloat16* sQl = sQh + FTILE;
    __nv_bfloat16* sKh = sQl + FTILE;
    __nv_bfloat16* sKl = sKh + FTILE;
    __nv_bfloat16* sVh = sKl + FTILE;
    __nv_bfloat16* sVl = sVh + FTILE;

    const int tid  = threadIdx.x;
    const int lane = tid & 31;
    const int wid  = tid >> 5;        // 0..3
    const int wm   = wid * 16;        // warp q-row offset
    const int qb   = blockIdx.x;
    const int h    = blockIdx.y;
    const int kh   = h >> 2;

    // fragment address patterns (validated in gemm_bf16x2)
    const int a_row = ((lane >> 3) & 1) * 8 + (lane & 7);
    const int a_col = (lane >> 4) * 8;
    const int b_row = ((lane >> 4) & 1) * 8 + (lane & 7);
    const int b_col = ((lane >> 3) & 1) * 8;
    const int v_row = lane & 15;
    const int v_col = (lane >> 4) * 8;
    const int g     = lane >> 2;
    const int t2    = (lane & 3) * 2;

    // gmem<->smem copy mapping: 2 threads per row, 64 bf16 each (8 x uint4)
    const int cr = tid >> 1;          // 0..63
    const int cc = (tid & 1) * 64;    // 0 or 64

    // load Q tile (pre-scaled hi/lo)
    {
        const __nv_bfloat16* gq0 = Qh + (size_t)(qb * 64 + cr) * D_MODEL + h * HD + cc;
        const __nv_bfloat16* gq1 = Ql + (size_t)(qb * 64 + cr) * D_MODEL + h * HD + cc;
#pragma unroll
        for (int i = 0; i < 8; i++) {
            *(uint4*)&sQh[cr * FST + cc + i * 8] = *(const uint4*)(gq0 + i * 8);
            *(uint4*)&sQl[cr * FST + cc + i * 8] = *(const uint4*)(gq1 + i * 8);
        }
    }

    float o[16][4];
#pragma unroll
    for (int i = 0; i < 16; i++)
#pragma unroll
        for (int j = 0; j < 4; j++) o[i][j] = 0.f;
    float m0r = -1e30f, m1r = -1e30f, l0r = 0.f, l1r = 0.f;

    for (int jt = 0; jt <= qb; jt++) {
        const int j0 = jt * 64;
        __syncthreads();   // previous tile compute finished before overwrite
        {
            const __nv_bfloat16* k0 = Kh + (size_t)(j0 + cr) * KV_DIM + kh * HD + cc;
            const __nv_bfloat16* k1 = Kl + (size_t)(j0 + cr) * KV_DIM + kh * HD + cc;
            const __nv_bfloat16* v0 = Vh + (size_t)(j0 + cr) * KV_DIM + kh * HD + cc;
            const __nv_bfloat16* v1 = Vl + (size_t)(j0 + cr) * KV_DIM + kh * HD + cc;
#pragma unroll
            for (int i = 0; i < 8; i++) {
                *(uint4*)&sKh[cr * FST + cc + i * 8] = *(const uint4*)(k0 + i * 8);
                *(uint4*)&sKl[cr * FST + cc + i * 8] = *(const uint4*)(k1 + i * 8);
                *(uint4*)&sVh[cr * FST + cc + i * 8] = *(const uint4*)(v0 + i * 8);
                *(uint4*)&sVl[cr * FST + cc + i * 8] = *(const uint4*)(v1 + i * 8);
            }
        }
        __syncthreads();

        // ---- S = Q K^T  (16 x 64 per warp), split 3-mma ----
        float sa[8][4];
#pragma unroll
        for (int c = 0; c < 8; c++)
#pragma unroll
            for (int j = 0; j < 4; j++) sa[c][j] = 0.f;

#pragma unroll
        for (int kk = 0; kk < 8; kk++) {
            uint32_t qh0, qh1, qh2, qh3, ql0, ql1, ql2, ql3;
            ldmx4(qh0, qh1, qh2, qh3,
                  s2u(&sQh[(wm + a_row) * FST + kk * 16 + a_col]));
            ldmx4(ql0, ql1, ql2, ql3,
                  s2u(&sQl[(wm + a_row) * FST + kk * 16 + a_col]));
#pragma unroll
            for (int njp = 0; njp < 4; njp++) {
                uint32_t bh0, bh1, bh2, bh3, bl0, bl1, bl2, bl3;
                ldmx4(bh0, bh1, bh2, bh3,
                      s2u(&sKh[(njp * 16 + b_row) * FST + kk * 16 + b_col]));
                ldmx4(bl0, bl1, bl2, bl3,
                      s2u(&sKl[(njp * 16 + b_row) * FST + kk * 16 + b_col]));
                mma16816(sa[2 * njp], qh0, qh1, qh2, qh3, bh0, bh1);
                mma16816(sa[2 * njp], qh0, qh1, qh2, qh3, bl0, bl1);
                mma16816(sa[2 * njp], ql0, ql1, ql2, ql3, bh0, bh1);
                mma16816(sa[2 * njp + 1], qh0, qh1, qh2, qh3, bh2, bh3);
                mma16816(sa[2 * njp + 1], qh0, qh1, qh2, qh3, bl2, bl3);
                mma16816(sa[2 * njp + 1], ql0, ql1, ql2, ql3, bh2, bh3);
            }
        }

        // ---- causal mask on diagonal tile ----
        if (jt == qb) {
            const int qr0 = qb * 64 + wm + g;
            const int qr1 = qr0 + 8;
#pragma unroll
            for (int c = 0; c < 8; c++) {
                const int col = j0 + c * 8 + t2;
                if (col     > qr0) sa[c][0] = -1e30f;
                if (col + 1 > qr0) sa[c][1] = -1e30f;
                if (col     > qr1) sa[c][2] = -1e30f;
                if (col + 1 > qr1) sa[c][3] = -1e30f;
            }
        }

        // ---- online softmax (rows g and g+8) ----
        float rm0 = -1e30f, rm1 = -1e30f;
#pragma unroll
        for (int c = 0; c < 8; c++) {
            rm0 = fmaxf(rm0, fmaxf(sa[c][0], sa[c][1]));
            rm1 = fmaxf(rm1, fmaxf(sa[c][2], sa[c][3]));
        }
        rm0 = fmaxf(rm0, __shfl_xor_sync(0xffffffffu, rm0, 1));
        rm0 = fmaxf(rm0, __shfl_xor_sync(0xffffffffu, rm0, 2));
        rm1 = fmaxf(rm1, __shfl_xor_sync(0xffffffffu, rm1, 1));
        rm1 = fmaxf(rm1, __shfl_xor_sync(0xffffffffu, rm1, 2));

        const float mn0 = fmaxf(m0r, rm0);
        const float mn1 = fmaxf(m1r, rm1);
        const float al0 = __expf(m0r - mn0);
        const float al1 = __expf(m1r - mn1);

        float rs0 = 0.f, rs1 = 0.f;
#pragma unroll
        for (int c = 0; c < 8; c++) {
            sa[c][0] = __expf(sa[c][0] - mn0);
            sa[c][1] = __expf(sa[c][1] - mn0);
            sa[c][2] = __expf(sa[c][2] - mn1);
            sa[c][3] = __expf(sa[c][3] - mn1);
            rs0 += sa[c][0] + sa[c][1];
            rs1 += sa[c][2] + sa[c][3];
        }
        rs0 += __shfl_xor_sync(0xffffffffu, rs0, 1);
        rs0 += __shfl_xor_sync(0xffffffffu, rs0, 2);
        rs1 += __shfl_xor_sync(0xffffffffu, rs1, 1);
        rs1 += __shfl_xor_sync(0xffffffffu, rs1, 2);

        l0r = l0r * al0 + rs0;
        l1r = l1r * al1 + rs1;
        m0r = mn0;
        m1r = mn1;
#pragma unroll
        for (int dj = 0; dj < 16; dj++) {
            o[dj][0] *= al0;
            o[dj][1] *= al0;
            o[dj][2] *= al1;
            o[dj][3] *= al1;
        }

        // ---- O += P V  (P from S accumulators, split) ----
#pragma unroll
        for (int ks = 0; ks < 4; ks++) {
            const int c0 = 2 * ks, c1 = 2 * ks + 1;
            uint32_t pl0, pl1, pl2, pl3;
            const uint32_t ph0 = pack_hl(sa[c0][0], sa[c0][1], pl0);
            const uint32_t ph1 = pack_hl(sa[c0][2], sa[c0][3], pl1);
            const uint32_t ph2 = pack_hl(sa[c1][0], sa[c1][1], pl2);
            const uint32_t ph3 = pack_hl(sa[c1][2], sa[c1][3], pl3);
#pragma unroll
            for (int djp = 0; djp < 8; djp++) {
                uint32_t vh0, vh1, vh2, vh3, vl0, vl1, vl2, vl3;
                ldmx4t(vh0, vh1, vh2, vh3,
                       s2u(&sVh[(ks * 16 + v_row) * FST + djp * 16 + v_col]));
                ldmx4t(vl0, vl1, vl2, vl3,
                       s2u(&sVl[(ks * 16 + v_row) * FST + djp * 16 + v_col]));
                mma16816(o[2 * djp], ph0, ph1, ph2, ph3, vh0, vh1);
                mma16816(o[2 * djp], ph0, ph1, ph2, ph3, vl0, vl1);
                mma16816(o[2 * djp], pl0, pl1, pl2, pl3, vh0, vh1);
                mma16816(o[2 * djp + 1], ph0, ph1, ph2, ph3, vh2, vh3);
                mma16816(o[2 * djp + 1], ph0, ph1, ph2, ph3, vl2, vl3);
                mma16816(o[2 * djp + 1], pl0, pl1, pl2, pl3, vh2, vh3);
            }
        }
    }

    // ---- write output ----
    const float inv0 = 1.0f / l0r;
    const float inv1 = 1.0f / l1r;
    const int row0 = qb * 64 + wm + g;
    const int row1 = row0 + 8;
#pragma unroll
    for (int dj = 0; dj < 16; dj++) {
        *(float2*)&AO[(size_t)row0 * D_MODEL + h * HD + dj * 8 + t2] =
            make_float2(o[dj][0] * inv0, o[dj][1] * inv0);
        *(float2*)&AO[(size_t)row1 * D_MODEL + h * HD + dj * 8 + t2] =
            make_float2(o[dj][2] * inv1, o[dj][3] * inv1);
    }
}

// ---------------------------------------------------------------------------
// launch — signature order: x, wq, wk, wv, wo
// ---------------------------------------------------------------------------
extern "C" void kernel_launch(void* const* d_in, const int* in_sizes, int n_in,
                              void* d_out, int out_size)
{
    const float* x  = (const float*)d_in[0];
    const float* wq = (const float*)d_in[1];
    const float* wk = (const float*)d_in[2];
    const float* wv = (const float*)d_in[3];
    const float* wo = (const float*)d_in[4];
    float* out = (float*)d_out;

    float *Qp, *Kp, *Vp, *Ap;
    __nv_bfloat16 *xh, *xl, *aoh, *aol, *wqh, *wql, *wkh, *wkl, *wvh, *wvl, *woh, *wol;
    __nv_bfloat16 *qhh, *qll, *khh, *kll, *vhh, *vll;
    cudaGetSymbolAddress((void**)&Qp,  g_Q);
    cudaGetSymbolAddress((void**)&Kp,  g_K);
    cudaGetSymbolAddress((void**)&Vp,  g_V);
    cudaGetSymbolAddress((void**)&Ap,  g_AO);
    cudaGetSymbolAddress((void**)&xh,  g_xh);  cudaGetSymbolAddress((void**)&xl,  g_xl);
    cudaGetSymbolAddress((void**)&aoh, g_aoh); cudaGetSymbolAddress((void**)&aol, g_aol);
    cudaGetSymbolAddress((void**)&wqh, g_wqh); cudaGetSymbolAddress((void**)&wql, g_wql);
    cudaGetSymbolAddress((void**)&wkh, g_wkh); cudaGetSymbolAddress((void**)&wkl, g_wkl);
    cudaGetSymbolAddress((void**)&wvh, g_wvh); cudaGetSymbolAddress((void**)&wvl, g_wvl);
    cudaGetSymbolAddress((void**)&woh, g_woh); cudaGetSymbolAddress((void**)&wol, g_wol);
    cudaGetSymbolAddress((void**)&qhh, g_Qh);  cudaGetSymbolAddress((void**)&qll, g_Ql);
    cudaGetSymbolAddress((void**)&khh, g_Kh);  cudaGetSymbolAddress((void**)&kll, g_Kl);
    cudaGetSymbolAddress((void**)&vhh, g_Vh);  cudaGetSymbolAddress((void**)&vll, g_Vl);

    const int smem_flash = 6 * FTILE * (int)sizeof(__nv_bfloat16);
    cudaFuncSetAttribute(flash2, cudaFuncAttributeMaxDynamicSharedMemorySize,
                         smem_flash);

    // input conversions
    conv_hilo<<<SZ_X / 1024, 256>>>(x, xh, xl, SZ_X, 1.0f);
    conv_t<<<dim3(D_MODEL / 32, D_MODEL / 32), dim3(32, 8)>>>(wq, wqh, wql, D_MODEL, D_MODEL);
    conv_t<<<dim3(KV_DIM / 32, D_MODEL / 32), dim3(32, 8)>>>(wk, wkh, wkl, D_MODEL, KV_DIM);
    conv_t<<<dim3(KV_DIM / 32, D_MODEL / 32), dim3(32, 8)>>>(wv, wvh, wvl, D_MODEL, KV_DIM);
    conv_t<<<dim3(D_MODEL / 32, D_MODEL / 32), dim3(32, 8)>>>(wo, woh, wol, D_MODEL, D_MODEL);

    // projections
    gemm_bf16x2<<<dim3(D_MODEL / 128, T_SEQ / 128), 256>>>(xh, xl, wqh, wql, Qp, T_SEQ, D_MODEL, D_MODEL);
    gemm_bf16x2<<<dim3(KV_DIM / 128, T_SEQ / 128), 256>>>(xh, xl, wkh, wkl, Kp, T_SEQ, KV_DIM, D_MODEL);
    gemm_bf16x2<<<dim3(KV_DIM / 128, T_SEQ / 128), 256>>>(xh, xl, wvh, wvl, Vp, T_SEQ, KV_DIM, D_MODEL);

    // RoPE
    rope2<<<T_SEQ, 256>>>(Qp, Kp);

    // split attention operands (Q pre-scaled)
    conv_hilo<<<SZ_X / 1024, 256>>>(Qp, qhh, qll, SZ_X, SCALE);
    conv_hilo<<<SZ_KV / 1024, 256>>>(Kp, khh, kll, SZ_KV, 1.0f);
    conv_hilo<<<SZ_KV / 1024, 256>>>(Vp, vhh, vll, SZ_KV, 1.0f);

    // attention (tensor cores)
    flash2<<<dim3(T_SEQ / 64, N_HEADS), 128, smem_flash>>>(qhh, qll, khh, kll, vhh, vll, Ap);

    // output projection
    conv_hilo<<<SZ_X / 1024, 256>>>(Ap, aoh, aol, SZ_X, 1.0f);
    gemm_bf16x2<<<dim3(D_MODEL / 128, T_SEQ / 128), 256>>>(aoh, aol, woh, wol, out, T_SEQ, D_MODEL, D_MODEL);
}

// round 10
// speedup vs baseline: 10.0265x; 1.0582x over previous
#include <cuda_runtime.h>
#include <cuda_bf16.h>
#include <math.h>
#include <stdint.h>

// ---------------------------------------------------------------------------
// LLaMA attention block (sm_103 non-'a' ISA: mma.sync + ldmatrix + cp.async).
// GEMMs: bf16x2 split MMA, 2-stage cp.async pipeline.
// Attention: bf16x2 split FA2 (validated R8).  RoPE: fp64 trig (validated).
// ---------------------------------------------------------------------------

#define T_SEQ   2048
#define D_MODEL 4096
#define KV_DIM  1024
#define N_HEADS 32
#define HD      128
#define SCALE   0.08838834764831845f   // 1/sqrt(128)

#define SZ_X    (T_SEQ * D_MODEL)
#define SZ_WQ   (D_MODEL * D_MODEL)
#define SZ_WK   (D_MODEL * KV_DIM)
#define SZ_KV   (T_SEQ * KV_DIM)

// fp32 scratch
__device__ float g_Q [SZ_X];
__device__ float g_K [SZ_KV];
__device__ float g_V [SZ_KV];
__device__ float g_AO[SZ_X];
// bf16 hi/lo scratch (weights TRANSPOSED: [N][K])
__device__ __nv_bfloat16 g_xh [SZ_X],  g_xl [SZ_X];
__device__ __nv_bfloat16 g_aoh[SZ_X],  g_aol[SZ_X];
__device__ __nv_bfloat16 g_wqh[SZ_WQ], g_wql[SZ_WQ];
__device__ __nv_bfloat16 g_wkh[SZ_WK], g_wkl[SZ_WK];
__device__ __nv_bfloat16 g_wvh[SZ_WK], g_wvl[SZ_WK];
__device__ __nv_bfloat16 g_woh[SZ_WQ], g_wol[SZ_WQ];
// attention operands, hi/lo
__device__ __nv_bfloat16 g_Qh[SZ_X],  g_Ql[SZ_X];
__device__ __nv_bfloat16 g_Kh[SZ_KV], g_Kl[SZ_KV];
__device__ __nv_bfloat16 g_Vh[SZ_KV], g_Vl[SZ_KV];

// ---------------------------------------------------------------------------
// helpers
// ---------------------------------------------------------------------------
__device__ __forceinline__ uint32_t s2u(const void* p) {
    return (uint32_t)__cvta_generic_to_shared(p);
}
__device__ __forceinline__ void ldmx4(uint32_t& r0, uint32_t& r1,
                                      uint32_t& r2, uint32_t& r3, uint32_t a) {
    asm volatile("ldmatrix.sync.aligned.m8n8.x4.shared.b16 {%0,%1,%2,%3},[%4];\n"
                 : "=r"(r0), "=r"(r1), "=r"(r2), "=r"(r3) : "r"(a));
}
__device__ __forceinline__ void ldmx4t(uint32_t& r0, uint32_t& r1,
                                       uint32_t& r2, uint32_t& r3, uint32_t a) {
    asm volatile("ldmatrix.sync.aligned.m8n8.x4.trans.shared.b16 {%0,%1,%2,%3},[%4];\n"
                 : "=r"(r0), "=r"(r1), "=r"(r2), "=r"(r3) : "r"(a));
}
__device__ __forceinline__ void mma16816(float* d, uint32_t a0, uint32_t a1,
                                         uint32_t a2, uint32_t a3,
                                         uint32_t b0, uint32_t b1) {
    asm volatile(
        "mma.sync.aligned.m16n8k16.row.col.f32.bf16.bf16.f32 "
        "{%0,%1,%2,%3},{%4,%5,%6,%7},{%8,%9},{%0,%1,%2,%3};\n"
        : "+f"(d[0]), "+f"(d[1]), "+f"(d[2]), "+f"(d[3])
        : "r"(a0), "r"(a1), "r"(a2), "r"(a3), "r"(b0), "r"(b1));
}
__device__ __forceinline__ void split_hl(float v, __nv_bfloat16& h, __nv_bfloat16& l) {
    h = __float2bfloat16(v);
    l = __float2bfloat16(v - __bfloat162float(h));
}
__device__ __forceinline__ uint32_t pack_hl(float a, float b, uint32_t& lo) {
    __nv_bfloat16 ha, la, hb, lb;
    split_hl(a, ha, la);
    split_hl(b, hb, lb);
    __nv_bfloat162 H; H.x = ha; H.y = hb;
    __nv_bfloat162 L; L.x = la; L.y = lb;
    lo = *(uint32_t*)&L;
    return *(uint32_t*)&H;
}
__device__ __forceinline__ void cpa16(uint32_t s, const void* g) {
    asm volatile("cp.async.cg.shared.global [%0], [%1], 16;" :: "r"(s), "l"(g));
}

// ---------------------------------------------------------------------------
// fp32 -> bf16 hi/lo (optionally scaled)
// ---------------------------------------------------------------------------
__global__ __launch_bounds__(256)
void conv_hilo(const float* __restrict__ s, __nv_bfloat16* __restrict__ h,
               __nv_bfloat16* __restrict__ l, int n, float scale)
{
    int i = (blockIdx.x * blockDim.x + threadIdx.x) * 4;
    if (i >= n) return;
    float4 v = *(const float4*)(s + i);
    __nv_bfloat16 hh[4], ll[4];
    split_hl(v.x * scale, hh[0], ll[0]);
    split_hl(v.y * scale, hh[1], ll[1]);
    split_hl(v.z * scale, hh[2], ll[2]);
    split_hl(v.w * scale, hh[3], ll[3]);
    *(uint2*)(h + i) = *(uint2*)hh;
    *(uint2*)(l + i) = *(uint2*)ll;
}

// ---------------------------------------------------------------------------
// conversion + transpose: W [K,N] fp32 -> Wt hi/lo [N,K] bf16
// ---------------------------------------------------------------------------
__global__ __launch_bounds__(256)
void conv_t(const float* __restrict__ w, __nv_bfloat16* __restrict__ th,
            __nv_bfloat16* __restrict__ tl, int K, int N)
{
    __shared__ float tile[32][33];
    const int n0 = blockIdx.x * 32, k0 = blockIdx.y * 32;
    const int tx = threadIdx.x, ty = threadIdx.y;
#pragma unroll
    for (int i = 0; i < 4; i++)
        tile[ty + 8 * i][tx] = w[(size_t)(k0 + ty + 8 * i) * N + n0 + tx];
    __syncthreads();
#pragma unroll
    for (int i = 0; i < 4; i++) {
        float v = tile[tx][ty + 8 * i];
        __nv_bfloat16 h, l;
        split_hl(v, h, l);
        size_t o = (size_t)(n0 + ty + 8 * i) * K + k0 + tx;
        th[o] = h;
        tl[o] = l;
    }
}

// ---------------------------------------------------------------------------
// bf16x2-split MMA GEMM, 2-stage cp.async pipeline.
// C[M,N] = A[M,K] * Bt^T (Bt stored [N][K]).  BM=BN=128, BK=32, 256 thr.
// Stage buffer: 4 matrices x (128 rows x 40-elem stride) bf16 = 40 KB.
// ---------------------------------------------------------------------------
#define GP_MATE 5120                    // elems per matrix buffer (128*40)
#define GP_STGE (4 * GP_MATE)           // elems per stage
#define GP_SMEM (2 * GP_STGE * 2)       // bytes total (81920)

__global__ __launch_bounds__(256)
void gemm_pipe(const __nv_bfloat16* __restrict__ Ah, const __nv_bfloat16* __restrict__ Al,
               const __nv_bfloat16* __restrict__ Bh, const __nv_bfloat16* __restrict__ Bl,
               float* __restrict__ C, int M, int N, int K)
{
    extern __shared__ __nv_bfloat16 smg[];
    const uint32_t smbase = s2u(smg);

    const int tid  = threadIdx.x;
    const int lane = tid & 31;
    const int wid  = tid >> 5;
    const int m0 = blockIdx.y * 128, n0 = blockIdx.x * 128;
    const int wm = (wid & 1) * 64;
    const int wn = (wid >> 1) * 32;

    // chunk mapping (2 chunks of 16B per thread per matrix)
    const int r0 = tid >> 2;                 // rows 0..63
    const int o0 = (tid & 3) * 8;            // col elems 0,8,16,24
    const int r1 = r0 + 64;                  // rows 64..127

    float acc[4][4][4];
#pragma unroll
    for (int a = 0; a < 4; a++)
#pragma unroll
        for (int b = 0; b < 4; b++)
#pragma unroll
            for (int c = 0; c < 4; c++) acc[a][b][c] = 0.f;

    const int a_row = ((lane >> 3) & 1) * 8 + (lane & 7);
    const int a_col = (lane >> 4) * 8;
    const int b_row = ((lane >> 4) & 1) * 8 + (lane & 7);
    const int b_col = ((lane >> 3) & 1) * 8;

    const int NI = K / 32;

#define GP_ISSUE(st, kk0)                                                       \
    do {                                                                        \
        const uint32_t sb = smbase + (st) * (GP_STGE * 2);                      \
        cpa16(sb + (r0 * 40 + o0) * 2,                                          \
              Ah + (size_t)(m0 + r0) * K + (kk0) + o0);                         \
        cpa16(sb + (r1 * 40 + o0) * 2,                                          \
              Ah + (size_t)(m0 + r1) * K + (kk0) + o0);                         \
        cpa16(sb + (GP_MATE + r0 * 40 + o0) * 2,                                \
              Al + (size_t)(m0 + r0) * K + (kk0) + o0);                         \
        cpa16(sb + (GP_MATE + r1 * 40 + o0) * 2,                                \
              Al + (size_t)(m0 + r1) * K + (kk0) + o0);                         \
        cpa16(sb + (2 * GP_MATE + r0 * 40 + o0) * 2,                            \
              Bh + (size_t)(n0 + r0) * K + (kk0) + o0);                         \
        cpa16(sb + (2 * GP_MATE + r1 * 40 + o0) * 2,                            \
              Bh + (size_t)(n0 + r1) * K + (kk0) + o0);                         \
        cpa16(sb + (3 * GP_MATE + r0 * 40 + o0) * 2,                            \
              Bl + (size_t)(n0 + r0) * K + (kk0) + o0);                         \
        cpa16(sb + (3 * GP_MATE + r1 * 40 + o0) * 2,                            \
              Bl + (size_t)(n0 + r1) * K + (kk0) + o0);                         \
        asm volatile("cp.async.commit_group;");                                 \
    } while (0)

    GP_ISSUE(0, 0);

    for (int it = 0; it < NI; it++) {
        const int st = it & 1;
        if (it + 1 < NI) {
            GP_ISSUE(it & 1 ? 0 : 1, (it + 1) * 32);
            asm volatile("cp.async.wait_group 1;");
        } else {
            asm volatile("cp.async.wait_group 0;");
        }
        __syncthreads();

        const __nv_bfloat16* pAh = smg + st * GP_STGE;
        const __nv_bfloat16* pAl = pAh + GP_MATE;
        const __nv_bfloat16* pBh = pAh + 2 * GP_MATE;
        const __nv_bfloat16* pBl = pAh + 3 * GP_MATE;

#pragma unroll
        for (int kk = 0; kk < 32; kk += 16) {
            uint32_t ah[4][4], al[4][4], bh[4][2], bl[4][2];
#pragma unroll
            for (int mi = 0; mi < 4; mi++) {
                ldmx4(ah[mi][0], ah[mi][1], ah[mi][2], ah[mi][3],
                      s2u(pAh + (wm + 16 * mi + a_row) * 40 + kk + a_col));
                ldmx4(al[mi][0], al[mi][1], al[mi][2], al[mi][3],
                      s2u(pAl + (wm + 16 * mi + a_row) * 40 + kk + a_col));
            }
#pragma unroll
            for (int nj = 0; nj < 2; nj++) {
                uint32_t t0, t1, t2, t3;
                ldmx4(t0, t1, t2, t3,
                      s2u(pBh + (wn + 16 * nj + b_row) * 40 + kk + b_col));
                bh[2 * nj][0] = t0; bh[2 * nj][1] = t1;
                bh[2 * nj + 1][0] = t2; bh[2 * nj + 1][1] = t3;
                ldmx4(t0, t1, t2, t3,
                      s2u(pBl + (wn + 16 * nj + b_row) * 40 + kk + b_col));
                bl[2 * nj][0] = t0; bl[2 * nj][1] = t1;
                bl[2 * nj + 1][0] = t2; bl[2 * nj + 1][1] = t3;
            }
#pragma unroll
            for (int mi = 0; mi < 4; mi++)
#pragma unroll
                for (int ni = 0; ni < 4; ni++) {
                    mma16816(acc[mi][ni], ah[mi][0], ah[mi][1], ah[mi][2], ah[mi][3],
                             bh[ni][0], bh[ni][1]);
                    mma16816(acc[mi][ni], ah[mi][0], ah[mi][1], ah[mi][2], ah[mi][3],
                             bl[ni][0], bl[ni][1]);
                    mma16816(acc[mi][ni], al[mi][0], al[mi][1], al[mi][2], al[mi][3],
                             bh[ni][0], bh[ni][1]);
                }
        }
        __syncthreads();
    }
#undef GP_ISSUE

    const int g  = lane >> 2;
    const int t2 = (lane & 3) * 2;
#pragma unroll
    for (int mi = 0; mi < 4; mi++)
#pragma unroll
        for (int ni = 0; ni < 4; ni++) {
            const int row = m0 + wm + 16 * mi + g;
            const int col = n0 + wn + 8 * ni + t2;
            *(float2*)&C[(size_t)row * N + col] =
                make_float2(acc[mi][ni][0], acc[mi][ni][1]);
            *(float2*)&C[(size_t)(row + 8) * N + col] =
                make_float2(acc[mi][ni][2], acc[mi][ni][3]);
        }
}

// ---------------------------------------------------------------------------
// RoPE, fp64 trig (validated)
// ---------------------------------------------------------------------------
__global__ __launch_bounds__(256)
void rope2(float* __restrict__ Q, float* __restrict__ K)
{
    const int t = blockIdx.x;
    for (int p = threadIdx.x; p < 40 * 64; p += blockDim.x) {
        const int h = p >> 6;
        const int j = p & 63;
        const double fj  = pow(10000.0, -(double)j / 64.0);
        const double ang = (double)t * fj;
        const float  c   = (float)cos(ang);
        const float  s   = (float)sin(ang);
        float* row;
        if (h < N_HEADS) row = Q + (size_t)t * D_MODEL + h * HD;
        else             row = K + (size_t)t * KV_DIM + (h - N_HEADS) * HD;
        const float v0 = row[j];
        const float v1 = row[j + 64];
        row[j]      = v0 * c - v1 * s;
        row[j + 64] = v1 * c + v0 * s;
    }
}

// ---------------------------------------------------------------------------
// Tensor-core flash attention (FA2), bf16x2 split (validated R8).
// ---------------------------------------------------------------------------
#define FST 136
#define FTILE (64 * FST)

__global__ __launch_bounds__(128)
void flash2(const __nv_bfloat16* __restrict__ Qh, const __nv_bfloat16* __restrict__ Ql,
            const __nv_bfloat16* __restrict__ Kh, const __nv_bfloat16* __restrict__ Kl,
            const __nv_bfloat16* __restrict__ Vh, const __nv_bfloat16* __restrict__ Vl,
            float* __restrict__ AO)
{
    extern __shared__ __nv_bfloat16 smf[];
    __nv_bfloat16* sQh = smf;
    __nv_bfloat16* sQl = sQh + FTILE;
    __nv_bfloat16* sKh = sQl + FTILE;
    __nv_bfloat16* sKl = sKh + FTILE;
    __nv_bfloat16* sVh = sKl + FTILE;
    __nv_bfloat16* sVl = sVh + FTILE;

    const int tid  = threadIdx.x;
    const int lane = tid & 31;
    const int wid  = tid >> 5;
    const int wm   = wid * 16;
    const int qb   = blockIdx.x;
    const int h    = blockIdx.y;
    const int kh   = h >> 2;

    const int a_row = ((lane >> 3) & 1) * 8 + (lane & 7);
    const int a_col = (lane >> 4) * 8;
    const int b_row = ((lane >> 4) & 1) * 8 + (lane & 7);
    const int b_col = ((lane >> 3) & 1) * 8;
    const int v_row = lane & 15;
    const int v_col = (lane >> 4) * 8;
    const int g     = lane >> 2;
    const int t2    = (lane & 3) * 2;

    const int cr = tid >> 1;
    const int cc = (tid & 1) * 64;

    {
        const __nv_bfloat16* gq0 = Qh + (size_t)(qb * 64 + cr) * D_MODEL + h * HD + cc;
        const __nv_bfloat16* gq1 = Ql + (size_t)(qb * 64 + cr) * D_MODEL + h * HD + cc;
#pragma unroll
        for (int i = 0; i < 8; i++) {
            *(uint4*)&sQh[cr * FST + cc + i * 8] = *(const uint4*)(gq0 + i * 8);
            *(uint4*)&sQl[cr * FST + cc + i * 8] = *(const uint4*)(gq1 + i * 8);
        }
    }

    float o[16][4];
#pragma unroll
    for (int i = 0; i < 16; i++)
#pragma unroll
        for (int j = 0; j < 4; j++) o[i][j] = 0.f;
    float m0r = -1e30f, m1r = -1e30f, l0r = 0.f, l1r = 0.f;

    for (int jt = 0; jt <= qb; jt++) {
        const int j0 = jt * 64;
        __syncthreads();
        {
            const __nv_bfloat16* k0 = Kh + (size_t)(j0 + cr) * KV_DIM + kh * HD + cc;
            const __nv_bfloat16* k1 = Kl + (size_t)(j0 + cr) * KV_DIM + kh * HD + cc;
            const __nv_bfloat16* v0 = Vh + (size_t)(j0 + cr) * KV_DIM + kh * HD + cc;
            const __nv_bfloat16* v1 = Vl + (size_t)(j0 + cr) * KV_DIM + kh * HD + cc;
#pragma unroll
            for (int i = 0; i < 8; i++) {
                *(uint4*)&sKh[cr * FST + cc + i * 8] = *(const uint4*)(k0 + i * 8);
                *(uint4*)&sKl[cr * FST + cc + i * 8] = *(const uint4*)(k1 + i * 8);
                *(uint4*)&sVh[cr * FST + cc + i * 8] = *(const uint4*)(v0 + i * 8);
                *(uint4*)&sVl[cr * FST + cc + i * 8] = *(const uint4*)(v1 + i * 8);
            }
        }
        __syncthreads();

        float sa[8][4];
#pragma unroll
        for (int c = 0; c < 8; c++)
#pragma unroll
            for (int j = 0; j < 4; j++) sa[c][j] = 0.f;

#pragma unroll
        for (int kk = 0; kk < 8; kk++) {
            uint32_t qh0, qh1, qh2, qh3, ql0, ql1, ql2, ql3;
            ldmx4(qh0, qh1, qh2, qh3, s2u(&sQh[(wm + a_row) * FST + kk * 16 + a_col]));
            ldmx4(ql0, ql1, ql2, ql3, s2u(&sQl[(wm + a_row) * FST + kk * 16 + a_col]));
#pragma unroll
            for (int njp = 0; njp < 4; njp++) {
                uint32_t bh0, bh1, bh2, bh3, bl0, bl1, bl2, bl3;
                ldmx4(bh0, bh1, bh2, bh3,
                      s2u(&sKh[(njp * 16 + b_row) * FST + kk * 16 + b_col]));
                ldmx4(bl0, bl1, bl2, bl3,
                      s2u(&sKl[(njp * 16 + b_row) * FST + kk * 16 + b_col]));
                mma16816(sa[2 * njp], qh0, qh1, qh2, qh3, bh0, bh1);
                mma16816(sa[2 * njp], qh0, qh1, qh2, qh3, bl0, bl1);
                mma16816(sa[2 * njp], ql0, ql1, ql2, ql3, bh0, bh1);
                mma16816(sa[2 * njp + 1], qh0, qh1, qh2, qh3, bh2, bh3);
                mma16816(sa[2 * njp + 1], qh0, qh1, qh2, qh3, bl2, bl3);
                mma16816(sa[2 * njp + 1], ql0, ql1, ql2, ql3, bh2, bh3);
            }
        }

        if (jt == qb) {
            const int qr0 = qb * 64 + wm + g;
            const int qr1 = qr0 + 8;
#pragma unroll
            for (int c = 0; c < 8; c++) {
                const int col = j0 + c * 8 + t2;
                if (col     > qr0) sa[c][0] = -1e30f;
                if (col + 1 > qr0) sa[c][1] = -1e30f;
                if (col     > qr1) sa[c][2] = -1e30f;
                if (col + 1 > qr1) sa[c][3] = -1e30f;
            }
        }

        float rm0 = -1e30f, rm1 = -1e30f;
#pragma unroll
        for (int c = 0; c < 8; c++) {
            rm0 = fmaxf(rm0, fmaxf(sa[c][0], sa[c][1]));
            rm1 = fmaxf(rm1, fmaxf(sa[c][2], sa[c][3]));
        }
        rm0 = fmaxf(rm0, __shfl_xor_sync(0xffffffffu, rm0, 1));
        rm0 = fmaxf(rm0, __shfl_xor_sync(0xffffffffu, rm0, 2));
        rm1 = fmaxf(rm1, __shfl_xor_sync(0xffffffffu, rm1, 1));
        rm1 = fmaxf(rm1, __shfl_xor_sync(0xffffffffu, rm1, 2));

        const float mn0 = fmaxf(m0r, rm0);
        const float mn1 = fmaxf(m1r, rm1);
        const float al0 = __expf(m0r - mn0);
        const float al1 = __expf(m1r - mn1);

        float rs0 = 0.f, rs1 = 0.f;
#pragma unroll
        for (int c = 0; c < 8; c++) {
            sa[c][0] = __expf(sa[c][0] - mn0);
            sa[c][1] = __expf(sa[c][1] - mn0);
            sa[c][2] = __expf(sa[c][2] - mn1);
            sa[c][3] = __expf(sa[c][3] - mn1);
            rs0 += sa[c][0] + sa[c][1];
            rs1 += sa[c][2] + sa[c][3];
        }
        rs0 += __shfl_xor_sync(0xffffffffu, rs0, 1);
        rs0 += __shfl_xor_sync(0xffffffffu, rs0, 2);
        rs1 += __shfl_xor_sync(0xffffffffu, rs1, 1);
        rs1 += __shfl_xor_sync(0xffffffffu, rs1, 2);

        l0r = l0r * al0 + rs0;
        l1r = l1r * al1 + rs1;
        m0r = mn0;
        m1r = mn1;
#pragma unroll
        for (int dj = 0; dj < 16; dj++) {
            o[dj][0] *= al0;
            o[dj][1] *= al0;
            o[dj][2] *= al1;
            o[dj][3] *= al1;
        }

#pragma unroll
        for (int ks = 0; ks < 4; ks++) {
            const int c0 = 2 * ks, c1 = 2 * ks + 1;
            uint32_t pl0, pl1, pl2, pl3;
            const uint32_t ph0 = pack_hl(sa[c0][0], sa[c0][1], pl0);
            const uint32_t ph1 = pack_hl(sa[c0][2], sa[c0][3], pl1);
            const uint32_t ph2 = pack_hl(sa[c1][0], sa[c1][1], pl2);
            const uint32_t ph3 = pack_hl(sa[c1][2], sa[c1][3], pl3);
#pragma unroll
            for (int djp = 0; djp < 8; djp++) {
                uint32_t vh0, vh1, vh2, vh3, vl0, vl1, vl2, vl3;
                ldmx4t(vh0, vh1, vh2, vh3,
                       s2u(&sVh[(ks * 16 + v_row) * FST + djp * 16 + v_col]));
                ldmx4t(vl0, vl1, vl2, vl3,
                       s2u(&sVl[(ks * 16 + v_row) * FST + djp * 16 + v_col]));
                mma16816(o[2 * djp], ph0, ph1, ph2, ph3, vh0, vh1);
                mma16816(o[2 * djp], ph0, ph1, ph2, ph3, vl0, vl1);
                mma16816(o[2 * djp], pl0, pl1, pl2, pl3, vh0, vh1);
                mma16816(o[2 * djp + 1], ph0, ph1, ph2, ph3, vh2, vh3);
                mma16816(o[2 * djp + 1], ph0, ph1, ph2, ph3, vl2, vl3);
                mma16816(o[2 * djp + 1], pl0, pl1, pl2, pl3, vh2, vh3);
            }
        }
    }

    const float inv0 = 1.0f / l0r;
    const float inv1 = 1.0f / l1r;
    const int row0 = qb * 64 + wm + g;
    const int row1 = row0 + 8;
#pragma unroll
    for (int dj = 0; dj < 16; dj++) {
        *(float2*)&AO[(size_t)row0 * D_MODEL + h * HD + dj * 8 + t2] =
            make_float2(o[dj][0] * inv0, o[dj][1] * inv0);
        *(float2*)&AO[(size_t)row1 * D_MODEL + h * HD + dj * 8 + t2] =
            make_float2(o[dj][2] * inv1, o[dj][3] * inv1);
    }
}

// ---------------------------------------------------------------------------
// launch — signature order: x, wq, wk, wv, wo
// ---------------------------------------------------------------------------
extern "C" void kernel_launch(void* const* d_in, const int* in_sizes, int n_in,
                              void* d_out, int out_size)
{
    const float* x  = (const float*)d_in[0];
    const float* wq = (const float*)d_in[1];
    const float* wk = (const float*)d_in[2];
    const float* wv = (const float*)d_in[3];
    const float* wo = (const float*)d_in[4];
    float* out = (float*)d_out;

    float *Qp, *Kp, *Vp, *Ap;
    __nv_bfloat16 *xh, *xl, *aoh, *aol, *wqh, *wql, *wkh, *wkl, *wvh, *wvl, *woh, *wol;
    __nv_bfloat16 *qhh, *qll, *khh, *kll, *vhh, *vll;
    cudaGetSymbolAddress((void**)&Qp,  g_Q);
    cudaGetSymbolAddress((void**)&Kp,  g_K);
    cudaGetSymbolAddress((void**)&Vp,  g_V);
    cudaGetSymbolAddress((void**)&Ap,  g_AO);
    cudaGetSymbolAddress((void**)&xh,  g_xh);  cudaGetSymbolAddress((void**)&xl,  g_xl);
    cudaGetSymbolAddress((void**)&aoh, g_aoh); cudaGetSymbolAddress((void**)&aol, g_aol);
    cudaGetSymbolAddress((void**)&wqh, g_wqh); cudaGetSymbolAddress((void**)&wql, g_wql);
    cudaGetSymbolAddress((void**)&wkh, g_wkh); cudaGetSymbolAddress((void**)&wkl, g_wkl);
    cudaGetSymbolAddress((void**)&wvh, g_wvh); cudaGetSymbolAddress((void**)&wvl, g_wvl);
    cudaGetSymbolAddress((void**)&woh, g_woh); cudaGetSymbolAddress((void**)&wol, g_wol);
    cudaGetSymbolAddress((void**)&qhh, g_Qh);  cudaGetSymbolAddress((void**)&qll, g_Ql);
    cudaGetSymbolAddress((void**)&khh, g_Kh);  cudaGetSymbolAddress((void**)&kll, g_Kl);
    cudaGetSymbolAddress((void**)&vhh, g_Vh);  cudaGetSymbolAddress((void**)&vll, g_Vl);

    const int smem_flash = 6 * FTILE * (int)sizeof(__nv_bfloat16);
    cudaFuncSetAttribute(flash2, cudaFuncAttributeMaxDynamicSharedMemorySize, smem_flash);
    cudaFuncSetAttribute(gemm_pipe, cudaFuncAttributeMaxDynamicSharedMemorySize, GP_SMEM);

    // input conversions
    conv_hilo<<<SZ_X / 1024, 256>>>(x, xh, xl, SZ_X, 1.0f);
    conv_t<<<dim3(D_MODEL / 32, D_MODEL / 32), dim3(32, 8)>>>(wq, wqh, wql, D_MODEL, D_MODEL);
    conv_t<<<dim3(KV_DIM / 32, D_MODEL / 32), dim3(32, 8)>>>(wk, wkh, wkl, D_MODEL, KV_DIM);
    conv_t<<<dim3(KV_DIM / 32, D_MODEL / 32), dim3(32, 8)>>>(wv, wvh, wvl, D_MODEL, KV_DIM);
    conv_t<<<dim3(D_MODEL / 32, D_MODEL / 32), dim3(32, 8)>>>(wo, woh, wol, D_MODEL, D_MODEL);

    // projections
    gemm_pipe<<<dim3(D_MODEL / 128, T_SEQ / 128), 256, GP_SMEM>>>(xh, xl, wqh, wql, Qp, T_SEQ, D_MODEL, D_MODEL);
    gemm_pipe<<<dim3(KV_DIM / 128, T_SEQ / 128), 256, GP_SMEM>>>(xh, xl, wkh, wkl, Kp, T_SEQ, KV_DIM, D_MODEL);
    gemm_pipe<<<dim3(KV_DIM / 128, T_SEQ / 128), 256, GP_SMEM>>>(xh, xl, wvh, wvl, Vp, T_SEQ, KV_DIM, D_MODEL);

    // RoPE
    rope2<<<T_SEQ, 256>>>(Qp, Kp);

    // split attention operands (Q pre-scaled)
    conv_hilo<<<SZ_X / 1024, 256>>>(Qp, qhh, qll, SZ_X, SCALE);
    conv_hilo<<<SZ_KV / 1024, 256>>>(Kp, khh, kll, SZ_KV, 1.0f);
    conv_hilo<<<SZ_KV / 1024, 256>>>(Vp, vhh, vll, SZ_KV, 1.0f);

    // attention
    flash2<<<dim3(T_SEQ / 64, N_HEADS), 128, smem_flash>>>(qhh, qll, khh, kll, vhh, vll, Ap);

    // output projection
    conv_hilo<<<SZ_X / 1024, 256>>>(Ap, aoh, aol, SZ_X, 1.0f);
    gemm_pipe<<<dim3(D_MODEL / 128, T_SEQ / 128), 256, GP_SMEM>>>(aoh, aol, woh, wol, out, T_SEQ, D_MODEL, D_MODEL);
}

// round 11
// speedup vs baseline: 10.6580x; 1.0630x over previous
#include <cuda_runtime.h>
#include <cuda_bf16.h>
#include <math.h>
#include <stdint.h>

// ---------------------------------------------------------------------------
// LLaMA attention block (sm_103 non-'a' ISA: mma.sync + ldmatrix + cp.async).
// GEMMs: bf16x2 split MMA, 2-stage cp.async pipeline (validated R10).
// Attention: bf16x2 split FA2, BQ=128, cp.async-pipelined K/V (new).
// RoPE: fp64 trig (validated).
// ---------------------------------------------------------------------------

#define T_SEQ   2048
#define D_MODEL 4096
#define KV_DIM  1024
#define KV2     2048                  // concat K|V row width
#define N_HEADS 32
#define HD      128
#define SCALE   0.08838834764831845f  // 1/sqrt(128)

#define SZ_X    (T_SEQ * D_MODEL)
#define SZ_WQ   (D_MODEL * D_MODEL)
#define SZ_WK   (D_MODEL * KV_DIM)
#define SZ_KV2  (T_SEQ * KV2)

// fp32 scratch
__device__ float g_Q  [SZ_X];
__device__ float g_KV [SZ_KV2];       // K in cols [0,1024), V in [1024,2048)
__device__ float g_AO [SZ_X];
// bf16 hi/lo scratch (weights TRANSPOSED: [N][K]; wkv concatenated on N)
__device__ __nv_bfloat16 g_xh  [SZ_X],   g_xl  [SZ_X];
__device__ __nv_bfloat16 g_aoh [SZ_X],   g_aol [SZ_X];
__device__ __nv_bfloat16 g_wqh [SZ_WQ],  g_wql [SZ_WQ];
__device__ __nv_bfloat16 g_wkvh[2*SZ_WK],g_wkvl[2*SZ_WK];
__device__ __nv_bfloat16 g_woh [SZ_WQ],  g_wol [SZ_WQ];
// attention operands, hi/lo
__device__ __nv_bfloat16 g_Qh [SZ_X],   g_Ql [SZ_X];
__device__ __nv_bfloat16 g_KVh[SZ_KV2], g_KVl[SZ_KV2];

// ---------------------------------------------------------------------------
// helpers
// ---------------------------------------------------------------------------
__device__ __forceinline__ uint32_t s2u(const void* p) {
    return (uint32_t)__cvta_generic_to_shared(p);
}
__device__ __forceinline__ void ldmx4(uint32_t& r0, uint32_t& r1,
                                      uint32_t& r2, uint32_t& r3, uint32_t a) {
    asm volatile("ldmatrix.sync.aligned.m8n8.x4.shared.b16 {%0,%1,%2,%3},[%4];\n"
                 : "=r"(r0), "=r"(r1), "=r"(r2), "=r"(r3) : "r"(a));
}
__device__ __forceinline__ void ldmx4t(uint32_t& r0, uint32_t& r1,
                                       uint32_t& r2, uint32_t& r3, uint32_t a) {
    asm volatile("ldmatrix.sync.aligned.m8n8.x4.trans.shared.b16 {%0,%1,%2,%3},[%4];\n"
                 : "=r"(r0), "=r"(r1), "=r"(r2), "=r"(r3) : "r"(a));
}
__device__ __forceinline__ void mma16816(float* d, uint32_t a0, uint32_t a1,
                                         uint32_t a2, uint32_t a3,
                                         uint32_t b0, uint32_t b1) {
    asm volatile(
        "mma.sync.aligned.m16n8k16.row.col.f32.bf16.bf16.f32 "
        "{%0,%1,%2,%3},{%4,%5,%6,%7},{%8,%9},{%0,%1,%2,%3};\n"
        : "+f"(d[0]), "+f"(d[1]), "+f"(d[2]), "+f"(d[3])
        : "r"(a0), "r"(a1), "r"(a2), "r"(a3), "r"(b0), "r"(b1));
}
__device__ __forceinline__ void split_hl(float v, __nv_bfloat16& h, __nv_bfloat16& l) {
    h = __float2bfloat16(v);
    l = __float2bfloat16(v - __bfloat162float(h));
}
__device__ __forceinline__ uint32_t pack_hl(float a, float b, uint32_t& lo) {
    __nv_bfloat16 ha, la, hb, lb;
    split_hl(a, ha, la);
    split_hl(b, hb, lb);
    __nv_bfloat162 H; H.x = ha; H.y = hb;
    __nv_bfloat162 L; L.x = la; L.y = lb;
    lo = *(uint32_t*)&L;
    return *(uint32_t*)&H;
}
__device__ __forceinline__ void cpa16(uint32_t s, const void* g) {
    asm volatile("cp.async.cg.shared.global [%0], [%1], 16;" :: "r"(s), "l"(g));
}

// ---------------------------------------------------------------------------
// fp32 -> bf16 hi/lo (optionally scaled)
// ---------------------------------------------------------------------------
__global__ __launch_bounds__(256)
void conv_hilo(const float* __restrict__ s, __nv_bfloat16* __restrict__ h,
               __nv_bfloat16* __restrict__ l, int n, float scale)
{
    int i = (blockIdx.x * blockDim.x + threadIdx.x) * 4;
    if (i >= n) return;
    float4 v = *(const float4*)(s + i);
    __nv_bfloat16 hh[4], ll[4];
    split_hl(v.x * scale, hh[0], ll[0]);
    split_hl(v.y * scale, hh[1], ll[1]);
    split_hl(v.z * scale, hh[2], ll[2]);
    split_hl(v.w * scale, hh[3], ll[3]);
    *(uint2*)(h + i) = *(uint2*)hh;
    *(uint2*)(l + i) = *(uint2*)ll;
}

// ---------------------------------------------------------------------------
// conversion + transpose: W [K,N] fp32 -> Wt hi/lo [N,K] bf16
// ---------------------------------------------------------------------------
__global__ __launch_bounds__(256)
void conv_t(const float* __restrict__ w, __nv_bfloat16* __restrict__ th,
            __nv_bfloat16* __restrict__ tl, int K, int N)
{
    __shared__ float tile[32][33];
    const int n0 = blockIdx.x * 32, k0 = blockIdx.y * 32;
    const int tx = threadIdx.x, ty = threadIdx.y;
#pragma unroll
    for (int i = 0; i < 4; i++)
        tile[ty + 8 * i][tx] = w[(size_t)(k0 + ty + 8 * i) * N + n0 + tx];
    __syncthreads();
#pragma unroll
    for (int i = 0; i < 4; i++) {
        float v = tile[tx][ty + 8 * i];
        __nv_bfloat16 h, l;
        split_hl(v, h, l);
        size_t o = (size_t)(n0 + ty + 8 * i) * K + k0 + tx;
        th[o] = h;
        tl[o] = l;
    }
}

// ---------------------------------------------------------------------------
// bf16x2-split MMA GEMM, 2-stage cp.async pipeline (validated R10).
// ---------------------------------------------------------------------------
#define GP_MATE 5120
#define GP_STGE (4 * GP_MATE)
#define GP_SMEM (2 * GP_STGE * 2)

__global__ __launch_bounds__(256)
void gemm_pipe(const __nv_bfloat16* __restrict__ Ah, const __nv_bfloat16* __restrict__ Al,
               const __nv_bfloat16* __restrict__ Bh, const __nv_bfloat16* __restrict__ Bl,
               float* __restrict__ C, int M, int N, int K)
{
    extern __shared__ __nv_bfloat16 smg[];
    const uint32_t smbase = s2u(smg);

    const int tid  = threadIdx.x;
    const int lane = tid & 31;
    const int wid  = tid >> 5;
    const int m0 = blockIdx.y * 128, n0 = blockIdx.x * 128;
    const int wm = (wid & 1) * 64;
    const int wn = (wid >> 1) * 32;

    const int r0 = tid >> 2;
    const int o0 = (tid & 3) * 8;
    const int r1 = r0 + 64;

    float acc[4][4][4];
#pragma unroll
    for (int a = 0; a < 4; a++)
#pragma unroll
        for (int b = 0; b < 4; b++)
#pragma unroll
            for (int c = 0; c < 4; c++) acc[a][b][c] = 0.f;

    const int a_row = ((lane >> 3) & 1) * 8 + (lane & 7);
    const int a_col = (lane >> 4) * 8;
    const int b_row = ((lane >> 4) & 1) * 8 + (lane & 7);
    const int b_col = ((lane >> 3) & 1) * 8;

    const int NI = K / 32;

#define GP_ISSUE(st, kk0)                                                       \
    do {                                                                        \
        const uint32_t sb = smbase + (st) * (GP_STGE * 2);                      \
        cpa16(sb + (r0 * 40 + o0) * 2, Ah + (size_t)(m0 + r0) * K + (kk0) + o0);\
        cpa16(sb + (r1 * 40 + o0) * 2, Ah + (size_t)(m0 + r1) * K + (kk0) + o0);\
        cpa16(sb + (GP_MATE + r0 * 40 + o0) * 2,                                \
              Al + (size_t)(m0 + r0) * K + (kk0) + o0);                         \
        cpa16(sb + (GP_MATE + r1 * 40 + o0) * 2,                                \
              Al + (size_t)(m0 + r1) * K + (kk0) + o0);                         \
        cpa16(sb + (2 * GP_MATE + r0 * 40 + o0) * 2,                            \
              Bh + (size_t)(n0 + r0) * K + (kk0) + o0);                         \
        cpa16(sb + (2 * GP_MATE + r1 * 40 + o0) * 2,                            \
              Bh + (size_t)(n0 + r1) * K + (kk0) + o0);                         \
        cpa16(sb + (3 * GP_MATE + r0 * 40 + o0) * 2,                            \
              Bl + (size_t)(n0 + r0) * K + (kk0) + o0);                         \
        cpa16(sb + (3 * GP_MATE + r1 * 40 + o0) * 2,                            \
              Bl + (size_t)(n0 + r1) * K + (kk0) + o0);                         \
        asm volatile("cp.async.commit_group;");                                 \
    } while (0)

    GP_ISSUE(0, 0);

    for (int it = 0; it < NI; it++) {
        const int st = it & 1;
        if (it + 1 < NI) {
            GP_ISSUE(it & 1 ? 0 : 1, (it + 1) * 32);
            asm volatile("cp.async.wait_group 1;");
        } else {
            asm volatile("cp.async.wait_group 0;");
        }
        __syncthreads();

        const __nv_bfloat16* pAh = smg + st * GP_STGE;
        const __nv_bfloat16* pAl = pAh + GP_MATE;
        const __nv_bfloat16* pBh = pAh + 2 * GP_MATE;
        const __nv_bfloat16* pBl = pAh + 3 * GP_MATE;

#pragma unroll
        for (int kk = 0; kk < 32; kk += 16) {
            uint32_t ah[4][4], al[4][4], bh[4][2], bl[4][2];
#pragma unroll
            for (int mi = 0; mi < 4; mi++) {
                ldmx4(ah[mi][0], ah[mi][1], ah[mi][2], ah[mi][3],
                      s2u(pAh + (wm + 16 * mi + a_row) * 40 + kk + a_col));
                ldmx4(al[mi][0], al[mi][1], al[mi][2], al[mi][3],
                      s2u(pAl + (wm + 16 * mi + a_row) * 40 + kk + a_col));
            }
#pragma unroll
            for (int nj = 0; nj < 2; nj++) {
                uint32_t t0, t1, t2, t3;
                ldmx4(t0, t1, t2, t3,
                      s2u(pBh + (wn + 16 * nj + b_row) * 40 + kk + b_col));
                bh[2 * nj][0] = t0; bh[2 * nj][1] = t1;
                bh[2 * nj + 1][0] = t2; bh[2 * nj + 1][1] = t3;
                ldmx4(t0, t1, t2, t3,
                      s2u(pBl + (wn + 16 * nj + b_row) * 40 + kk + b_col));
                bl[2 * nj][0] = t0; bl[2 * nj][1] = t1;
                bl[2 * nj + 1][0] = t2; bl[2 * nj + 1][1] = t3;
            }
#pragma unroll
            for (int mi = 0; mi < 4; mi++)
#pragma unroll
                for (int ni = 0; ni < 4; ni++) {
                    mma16816(acc[mi][ni], ah[mi][0], ah[mi][1], ah[mi][2], ah[mi][3],
                             bh[ni][0], bh[ni][1]);
                    mma16816(acc[mi][ni], ah[mi][0], ah[mi][1], ah[mi][2], ah[mi][3],
                             bl[ni][0], bl[ni][1]);
                    mma16816(acc[mi][ni], al[mi][0], al[mi][1], al[mi][2], al[mi][3],
                             bh[ni][0], bh[ni][1]);
                }
        }
        __syncthreads();
    }
#undef GP_ISSUE

    const int g  = lane >> 2;
    const int t2 = (lane & 3) * 2;
#pragma unroll
    for (int mi = 0; mi < 4; mi++)
#pragma unroll
        for (int ni = 0; ni < 4; ni++) {
            const int row = m0 + wm + 16 * mi + g;
            const int col = n0 + wn + 8 * ni + t2;
            *(float2*)&C[(size_t)row * N + col] =
                make_float2(acc[mi][ni][0], acc[mi][ni][1]);
            *(float2*)&C[(size_t)(row + 8) * N + col] =
                make_float2(acc[mi][ni][2], acc[mi][ni][3]);
        }
}

// ---------------------------------------------------------------------------
// RoPE, fp64 trig.  Q rows stride 4096; K lives in g_KV (stride 2048).
// ---------------------------------------------------------------------------
__global__ __launch_bounds__(256)
void rope2(float* __restrict__ Q, float* __restrict__ KV)
{
    const int t = blockIdx.x;
    for (int p = threadIdx.x; p < 40 * 64; p += blockDim.x) {
        const int h = p >> 6;
        const int j = p & 63;
        const double fj  = pow(10000.0, -(double)j / 64.0);
        const double ang = (double)t * fj;
        const float  c   = (float)cos(ang);
        const float  s   = (float)sin(ang);
        float* row;
        if (h < N_HEADS) row = Q + (size_t)t * D_MODEL + h * HD;
        else             row = KV + (size_t)t * KV2 + (h - N_HEADS) * HD;
        const float v0 = row[j];
        const float v1 = row[j + 64];
        row[j]      = v0 * c - v1 * s;
        row[j + 64] = v1 * c + v0 * s;
    }
}

// ---------------------------------------------------------------------------
// Flash attention FA2, bf16x2 split, BQ=128, BK=64, 256 thr (8 warps),
// 2-stage cp.async pipeline on K/V.  K|V concatenated (stride KV2).
// ---------------------------------------------------------------------------
#define FST  136
#define QT   (128 * FST)              // Q tile elems (one of hi/lo)
#define KVT  (64 * FST)               // K or V tile elems

// smem layout (bf16 elems): [Qh][Ql][stage0: Kh Kl Vh Vl][stage1: ...]
#define F3_SMEM ((2 * QT + 8 * KVT) * 2)

__global__ __launch_bounds__(256)
void flash3(const __nv_bfloat16* __restrict__ Qh, const __nv_bfloat16* __restrict__ Ql,
            const __nv_bfloat16* __restrict__ KVh, const __nv_bfloat16* __restrict__ KVl,
            float* __restrict__ AO)
{
    extern __shared__ __nv_bfloat16 smf[];
    __nv_bfloat16* sQh = smf;
    __nv_bfloat16* sQl = sQh + QT;
    __nv_bfloat16* sKV = sQl + QT;       // stages
    const uint32_t kvbase = s2u(sKV);

    const int tid  = threadIdx.x;
    const int lane = tid & 31;
    const int wid  = tid >> 5;          // 0..7
    const int wm   = wid * 16;          // warp q-row offset (0..112)
    const int qb   = blockIdx.x;        // q block of 128 rows
    const int h    = blockIdx.y;
    const int kh   = h >> 2;

    const int a_row = ((lane >> 3) & 1) * 8 + (lane & 7);
    const int a_col = (lane >> 4) * 8;
    const int b_row = ((lane >> 4) & 1) * 8 + (lane & 7);
    const int b_col = ((lane >> 3) & 1) * 8;
    const int v_row = lane & 15;
    const int v_col = (lane >> 4) * 8;
    const int g     = lane >> 2;
    const int t2    = (lane & 3) * 2;

    // Q copy: 2 thr/row, 64 elems each
    const int qr = tid >> 1;
    const int qc = (tid & 1) * 64;
    {
        const __nv_bfloat16* gq0 = Qh + (size_t)(qb * 128 + qr) * D_MODEL + h * HD + qc;
        const __nv_bfloat16* gq1 = Ql + (size_t)(qb * 128 + qr) * D_MODEL + h * HD + qc;
#pragma unroll
        for (int i = 0; i < 8; i++) {
            *(uint4*)&sQh[qr * FST + qc + i * 8] = *(const uint4*)(gq0 + i * 8);
            *(uint4*)&sQl[qr * FST + qc + i * 8] = *(const uint4*)(gq1 + i * 8);
        }
    }

    // K/V copy mapping: 4 thr/row (64 rows), 32 elems each
    const int kr = tid >> 2;
    const int kc = (tid & 3) * 32;
    const int ntiles = 2 * qb + 2;

#define F3_ISSUE(jtv)                                                            \
    do {                                                                         \
        const int _st = (jtv) & 1;                                               \
        const int _j0 = (jtv) * 64;                                              \
        const uint32_t sb = kvbase + _st * (4 * KVT) * 2;                        \
        const __nv_bfloat16* khg = KVh + (size_t)(_j0 + kr) * KV2 + kh * HD + kc;\
        const __nv_bfloat16* klg = KVl + (size_t)(_j0 + kr) * KV2 + kh * HD + kc;\
        const __nv_bfloat16* vhg = khg + KV_DIM;                                 \
        const __nv_bfloat16* vlg = klg + KV_DIM;                                 \
        _Pragma("unroll")                                                        \
        for (int i = 0; i < 4; i++) {                                            \
            const uint32_t so = (kr * FST + kc + i * 8) * 2;                     \
            cpa16(sb + so,               khg + i * 8);                           \
            cpa16(sb + KVT * 2 + so,     klg + i * 8);                           \
            cpa16(sb + 2 * KVT * 2 + so, vhg + i * 8);                           \
            cpa16(sb + 3 * KVT * 2 + so, vlg + i * 8);                           \
        }                                                                        \
        asm volatile("cp.async.commit_group;");                                  \
    } while (0)

    float o[16][4];
#pragma unroll
    for (int i = 0; i < 16; i++)
#pragma unroll
        for (int j = 0; j < 4; j++) o[i][j] = 0.f;
    float m0r = -1e30f, m1r = -1e30f, l0r = 0.f, l1r = 0.f;

    F3_ISSUE(0);

    for (int jt = 0; jt < ntiles; jt++) {
        const int st = jt & 1;
        const int j0 = jt * 64;
        if (jt + 1 < ntiles) {
            F3_ISSUE(jt + 1);
            asm volatile("cp.async.wait_group 1;");
        } else {
            asm volatile("cp.async.wait_group 0;");
        }
        __syncthreads();

        const __nv_bfloat16* sKh = sKV + st * 4 * KVT;
        const __nv_bfloat16* sKl = sKh + KVT;
        const __nv_bfloat16* sVh = sKh + 2 * KVT;
        const __nv_bfloat16* sVl = sKh + 3 * KVT;

        // ---- S = Q K^T (16 x 64 per warp), split 3-mma ----
        float sa[8][4];
#pragma unroll
        for (int c = 0; c < 8; c++)
#pragma unroll
            for (int j = 0; j < 4; j++) sa[c][j] = 0.f;

#pragma unroll
        for (int kk = 0; kk < 8; kk++) {
            uint32_t qh0, qh1, qh2, qh3, ql0, ql1, ql2, ql3;
            ldmx4(qh0, qh1, qh2, qh3, s2u(&sQh[(wm + a_row) * FST + kk * 16 + a_col]));
            ldmx4(ql0, ql1, ql2, ql3, s2u(&sQl[(wm + a_row) * FST + kk * 16 + a_col]));
#pragma unroll
            for (int njp = 0; njp < 4; njp++) {
                uint32_t bh0, bh1, bh2, bh3, bl0, bl1, bl2, bl3;
                ldmx4(bh0, bh1, bh2, bh3,
                      s2u(sKh + (njp * 16 + b_row) * FST + kk * 16 + b_col));
                ldmx4(bl0, bl1, bl2, bl3,
                      s2u(sKl + (njp * 16 + b_row) * FST + kk * 16 + b_col));
                mma16816(sa[2 * njp], qh0, qh1, qh2, qh3, bh0, bh1);
                mma16816(sa[2 * njp], qh0, qh1, qh2, qh3, bl0, bl1);
                mma16816(sa[2 * njp], ql0, ql1, ql2, ql3, bh0, bh1);
                mma16816(sa[2 * njp + 1], qh0, qh1, qh2, qh3, bh2, bh3);
                mma16816(sa[2 * njp + 1], qh0, qh1, qh2, qh3, bl2, bl3);
                mma16816(sa[2 * njp + 1], ql0, ql1, ql2, ql3, bh2, bh3);
            }
        }

        // ---- causal mask (possible only on last two k-tiles) ----
        if (jt >= ntiles - 2) {
            const int qr0 = qb * 128 + wm + g;
            const int qr1 = qr0 + 8;
#pragma unroll
            for (int c = 0; c < 8; c++) {
                const int col = j0 + c * 8 + t2;
                if (col     > qr0) sa[c][0] = -1e30f;
                if (col + 1 > qr0) sa[c][1] = -1e30f;
                if (col     > qr1) sa[c][2] = -1e30f;
                if (col + 1 > qr1) sa[c][3] = -1e30f;
            }
        }

        // ---- online softmax ----
        float rm0 = -1e30f, rm1 = -1e30f;
#pragma unroll
        for (int c = 0; c < 8; c++) {
            rm0 = fmaxf(rm0, fmaxf(sa[c][0], sa[c][1]));
            rm1 = fmaxf(rm1, fmaxf(sa[c][2], sa[c][3]));
        }
        rm0 = fmaxf(rm0, __shfl_xor_sync(0xffffffffu, rm0, 1));
        rm0 = fmaxf(rm0, __shfl_xor_sync(0xffffffffu, rm0, 2));
        rm1 = fmaxf(rm1, __shfl_xor_sync(0xffffffffu, rm1, 1));
        rm1 = fmaxf(rm1, __shfl_xor_sync(0xffffffffu, rm1, 2));

        const float mn0 = fmaxf(m0r, rm0);
        const float mn1 = fmaxf(m1r, rm1);
        const float al0 = __expf(m0r - mn0);
        const float al1 = __expf(m1r - mn1);

        float rs0 = 0.f, rs1 = 0.f;
#pragma unroll
        for (int c = 0; c < 8; c++) {
            sa[c][0] = __expf(sa[c][0] - mn0);
            sa[c][1] = __expf(sa[c][1] - mn0);
            sa[c][2] = __expf(sa[c][2] - mn1);
            sa[c][3] = __expf(sa[c][3] - mn1);
            rs0 += sa[c][0] + sa[c][1];
            rs1 += sa[c][2] + sa[c][3];
        }
        rs0 += __shfl_xor_sync(0xffffffffu, rs0, 1);
        rs0 += __shfl_xor_sync(0xffffffffu, rs0, 2);
        rs1 += __shfl_xor_sync(0xffffffffu, rs1, 1);
        rs1 += __shfl_xor_sync(0xffffffffu, rs1, 2);

        l0r = l0r * al0 + rs0;
        l1r = l1r * al1 + rs1;
        m0r = mn0;
        m1r = mn1;
#pragma unroll
        for (int dj = 0; dj < 16; dj++) {
            o[dj][0] *= al0;
            o[dj][1] *= al0;
            o[dj][2] *= al1;
            o[dj][3] *= al1;
        }

        // ---- O += P V ----
#pragma unroll
        for (int ks = 0; ks < 4; ks++) {
            const int c0 = 2 * ks, c1 = 2 * ks + 1;
            uint32_t pl0, pl1, pl2, pl3;
            const uint32_t ph0 = pack_hl(sa[c0][0], sa[c0][1], pl0);
            const uint32_t ph1 = pack_hl(sa[c0][2], sa[c0][3], pl1);
            const uint32_t ph2 = pack_hl(sa[c1][0], sa[c1][1], pl2);
            const uint32_t ph3 = pack_hl(sa[c1][2], sa[c1][3], pl3);
#pragma unroll
            for (int djp = 0; djp < 8; djp++) {
                uint32_t vh0, vh1, vh2, vh3, vl0, vl1, vl2, vl3;
                ldmx4t(vh0, vh1, vh2, vh3,
                       s2u(sVh + (ks * 16 + v_row) * FST + djp * 16 + v_col));
                ldmx4t(vl0, vl1, vl2, vl3,
                       s2u(sVl + (ks * 16 + v_row) * FST + djp * 16 + v_col));
                mma16816(o[2 * djp], ph0, ph1, ph2, ph3, vh0, vh1);
                mma16816(o[2 * djp], ph0, ph1, ph2, ph3, vl0, vl1);
                mma16816(o[2 * djp], pl0, pl1, pl2, pl3, vh0, vh1);
                mma16816(o[2 * djp + 1], ph0, ph1, ph2, ph3, vh2, vh3);
                mma16816(o[2 * djp + 1], ph0, ph1, ph2, ph3, vl2, vl3);
                mma16816(o[2 * djp + 1], pl0, pl1, pl2, pl3, vh2, vh3);
            }
        }
        __syncthreads();   // protect stage buffer before next ISSUE overwrites
    }
#undef F3_ISSUE

    const float inv0 = 1.0f / l0r;
    const float inv1 = 1.0f / l1r;
    const int row0 = qb * 128 + wm + g;
    const int row1 = row0 + 8;
#pragma unroll
    for (int dj = 0; dj < 16; dj++) {
        *(float2*)&AO[(size_t)row0 * D_MODEL + h * HD + dj * 8 + t2] =
            make_float2(o[dj][0] * inv0, o[dj][1] * inv0);
        *(float2*)&AO[(size_t)row1 * D_MODEL + h * HD + dj * 8 + t2] =
            make_float2(o[dj][2] * inv1, o[dj][3] * inv1);
    }
}

// ---------------------------------------------------------------------------
// launch — signature order: x, wq, wk, wv, wo
// ---------------------------------------------------------------------------
extern "C" void kernel_launch(void* const* d_in, const int* in_sizes, int n_in,
                              void* d_out, int out_size)
{
    const float* x  = (const float*)d_in[0];
    const float* wq = (const float*)d_in[1];
    const float* wk = (const float*)d_in[2];
    const float* wv = (const float*)d_in[3];
    const float* wo = (const float*)d_in[4];
    float* out = (float*)d_out;

    float *Qp, *KVp, *Ap;
    __nv_bfloat16 *xh, *xl, *aoh, *aol, *wqh, *wql, *wkvh, *wkvl, *woh, *wol;
    __nv_bfloat16 *qhh, *qll, *kvh, *kvl;
    cudaGetSymbolAddress((void**)&Qp,   g_Q);
    cudaGetSymbolAddress((void**)&KVp,  g_KV);
    cudaGetSymbolAddress((void**)&Ap,   g_AO);
    cudaGetSymbolAddress((void**)&xh,   g_xh);   cudaGetSymbolAddress((void**)&xl,   g_xl);
    cudaGetSymbolAddress((void**)&aoh,  g_aoh);  cudaGetSymbolAddress((void**)&aol,  g_aol);
    cudaGetSymbolAddress((void**)&wqh,  g_wqh);  cudaGetSymbolAddress((void**)&wql,  g_wql);
    cudaGetSymbolAddress((void**)&wkvh, g_wkvh); cudaGetSymbolAddress((void**)&wkvl, g_wkvl);
    cudaGetSymbolAddress((void**)&woh,  g_woh);  cudaGetSymbolAddress((void**)&wol,  g_wol);
    cudaGetSymbolAddress((void**)&qhh,  g_Qh);   cudaGetSymbolAddress((void**)&qll,  g_Ql);
    cudaGetSymbolAddress((void**)&kvh,  g_KVh);  cudaGetSymbolAddress((void**)&kvl,  g_KVl);

    cudaFuncSetAttribute(gemm_pipe, cudaFuncAttributeMaxDynamicSharedMemorySize, GP_SMEM);
    cudaFuncSetAttribute(flash3, cudaFuncAttributeMaxDynamicSharedMemorySize, F3_SMEM);

    // input conversions (wk rows -> wkv[0:1024], wv rows -> wkv[1024:2048])
    conv_hilo<<<SZ_X / 1024, 256>>>(x, xh, xl, SZ_X, 1.0f);
    conv_t<<<dim3(D_MODEL / 32, D_MODEL / 32), dim3(32, 8)>>>(wq, wqh, wql, D_MODEL, D_MODEL);
    conv_t<<<dim3(KV_DIM / 32, D_MODEL / 32), dim3(32, 8)>>>(wk, wkvh, wkvl, D_MODEL, KV_DIM);
    conv_t<<<dim3(KV_DIM / 32, D_MODEL / 32), dim3(32, 8)>>>(wv, wkvh + (size_t)KV_DIM * D_MODEL,
                                                             wkvl + (size_t)KV_DIM * D_MODEL,
                                                             D_MODEL, KV_DIM);
    conv_t<<<dim3(D_MODEL / 32, D_MODEL / 32), dim3(32, 8)>>>(wo, woh, wol, D_MODEL, D_MODEL);

    // projections (Q, then merged K|V)
    gemm_pipe<<<dim3(D_MODEL / 128, T_SEQ / 128), 256, GP_SMEM>>>(xh, xl, wqh, wql, Qp, T_SEQ, D_MODEL, D_MODEL);
    gemm_pipe<<<dim3(KV2 / 128, T_SEQ / 128), 256, GP_SMEM>>>(xh, xl, wkvh, wkvl, KVp, T_SEQ, KV2, D_MODEL);

    // RoPE
    rope2<<<T_SEQ, 256>>>(Qp, KVp);

    // split attention operands (Q pre-scaled)
    conv_hilo<<<SZ_X / 1024, 256>>>(Qp, qhh, qll, SZ_X, SCALE);
    conv_hilo<<<SZ_KV2 / 1024, 256>>>(KVp, kvh, kvl, SZ_KV2, 1.0f);

    // attention
    flash3<<<dim3(T_SEQ / 128, N_HEADS), 256, F3_SMEM>>>(qhh, qll, kvh, kvl, Ap);

    // output projection
    conv_hilo<<<SZ_X / 1024, 256>>>(Ap, aoh, aol, SZ_X, 1.0f);
    gemm_pipe<<<dim3(D_MODEL / 128, T_SEQ / 128), 256, GP_SMEM>>>(aoh, aol, woh, wol, out, T_SEQ, D_MODEL, D_MODEL);
}

// round 12
// speedup vs baseline: 16.0922x; 1.5099x over previous
#include <cuda_runtime.h>
#include <cuda_bf16.h>
#include <math.h>
#include <stdint.h>

// ---------------------------------------------------------------------------
// LLaMA attention block (sm_103 non-'a' ISA: mma.sync + ldmatrix + cp.async).
// GEMMs: bf16x2 split MMA, 2-stage cp.async pipeline, fused epilogues
//        (RoPE + scale + hi/lo split in-register/smem, no fp32 intermediates).
// Attention: bf16x2 split FA2, BQ=128, pipelined K/V, bf16 hi/lo output.
// ---------------------------------------------------------------------------

#define T_SEQ   2048
#define D_MODEL 4096
#define KV_DIM  1024
#define KV2     2048
#define N_HEADS 32
#define HD      128
#define SCALE   0.08838834764831845f  // 1/sqrt(128)

#define SZ_X    (T_SEQ * D_MODEL)
#define SZ_WQ   (D_MODEL * D_MODEL)
#define SZ_WK   (D_MODEL * KV_DIM)
#define SZ_KV2  (T_SEQ * KV2)

// bf16 hi/lo scratch (weights TRANSPOSED: [N][K]; wkv concatenated on N)
__device__ __nv_bfloat16 g_xh  [SZ_X],   g_xl  [SZ_X];
__device__ __nv_bfloat16 g_aoh [SZ_X],   g_aol [SZ_X];
__device__ __nv_bfloat16 g_wqh [SZ_WQ],  g_wql [SZ_WQ];
__device__ __nv_bfloat16 g_wkvh[2*SZ_WK],g_wkvl[2*SZ_WK];
__device__ __nv_bfloat16 g_woh [SZ_WQ],  g_wol [SZ_WQ];
// attention operands, hi/lo (written by fused GEMM epilogues)
__device__ __nv_bfloat16 g_Qh [SZ_X],   g_Ql [SZ_X];
__device__ __nv_bfloat16 g_KVh[SZ_KV2], g_KVl[SZ_KV2];
// rope tables (fp64-built)
__device__ float g_ct[T_SEQ * 64];
__device__ float g_st[T_SEQ * 64];

// ---------------------------------------------------------------------------
// helpers
// ---------------------------------------------------------------------------
__device__ __forceinline__ uint32_t s2u(const void* p) {
    return (uint32_t)__cvta_generic_to_shared(p);
}
__device__ __forceinline__ void ldmx4(uint32_t& r0, uint32_t& r1,
                                      uint32_t& r2, uint32_t& r3, uint32_t a) {
    asm volatile("ldmatrix.sync.aligned.m8n8.x4.shared.b16 {%0,%1,%2,%3},[%4];\n"
                 : "=r"(r0), "=r"(r1), "=r"(r2), "=r"(r3) : "r"(a));
}
__device__ __forceinline__ void ldmx4t(uint32_t& r0, uint32_t& r1,
                                       uint32_t& r2, uint32_t& r3, uint32_t a) {
    asm volatile("ldmatrix.sync.aligned.m8n8.x4.trans.shared.b16 {%0,%1,%2,%3},[%4];\n"
                 : "=r"(r0), "=r"(r1), "=r"(r2), "=r"(r3) : "r"(a));
}
__device__ __forceinline__ void mma16816(float* d, uint32_t a0, uint32_t a1,
                                         uint32_t a2, uint32_t a3,
                                         uint32_t b0, uint32_t b1) {
    asm volatile(
        "mma.sync.aligned.m16n8k16.row.col.f32.bf16.bf16.f32 "
        "{%0,%1,%2,%3},{%4,%5,%6,%7},{%8,%9},{%0,%1,%2,%3};\n"
        : "+f"(d[0]), "+f"(d[1]), "+f"(d[2]), "+f"(d[3])
        : "r"(a0), "r"(a1), "r"(a2), "r"(a3), "r"(b0), "r"(b1));
}
__device__ __forceinline__ void split_hl(float v, __nv_bfloat16& h, __nv_bfloat16& l) {
    h = __float2bfloat16(v);
    l = __float2bfloat16(v - __bfloat162float(h));
}
__device__ __forceinline__ uint32_t pack_hl(float a, float b, uint32_t& lo) {
    __nv_bfloat16 ha, la, hb, lb;
    split_hl(a, ha, la);
    split_hl(b, hb, lb);
    __nv_bfloat162 H; H.x = ha; H.y = hb;
    __nv_bfloat162 L; L.x = la; L.y = lb;
    lo = *(uint32_t*)&L;
    return *(uint32_t*)&H;
}
__device__ __forceinline__ void cpa16(uint32_t s, const void* g) {
    asm volatile("cp.async.cg.shared.global [%0], [%1], 16;" :: "r"(s), "l"(g));
}

// ---------------------------------------------------------------------------
// rope tables (fp64 trig, computed once)
// ---------------------------------------------------------------------------
__global__ void rope_tab(float* __restrict__ ct, float* __restrict__ st)
{
    const int t = blockIdx.x;
    const int j = threadIdx.x;           // 64 threads
    const double fj = pow(10000.0, -(double)j / 64.0);
    const double a  = (double)t * fj;
    ct[t * 64 + j] = (float)cos(a);
    st[t * 64 + j] = (float)sin(a);
}

// ---------------------------------------------------------------------------
// fp32 -> bf16 hi/lo, 8 elems/thread
// ---------------------------------------------------------------------------
__global__ __launch_bounds__(256)
void conv_hilo8(const float* __restrict__ s, __nv_bfloat16* __restrict__ h,
                __nv_bfloat16* __restrict__ l, int n)
{
    int i = (blockIdx.x * blockDim.x + threadIdx.x) * 8;
    if (i >= n) return;
    float4 v0 = *(const float4*)(s + i);
    float4 v1 = *(const float4*)(s + i + 4);
    __nv_bfloat16 hh[8], ll[8];
    split_hl(v0.x, hh[0], ll[0]); split_hl(v0.y, hh[1], ll[1]);
    split_hl(v0.z, hh[2], ll[2]); split_hl(v0.w, hh[3], ll[3]);
    split_hl(v1.x, hh[4], ll[4]); split_hl(v1.y, hh[5], ll[5]);
    split_hl(v1.z, hh[6], ll[6]); split_hl(v1.w, hh[7], ll[7]);
    *(uint4*)(h + i) = *(uint4*)hh;
    *(uint4*)(l + i) = *(uint4*)ll;
}

// ---------------------------------------------------------------------------
// conversion + transpose: W [K,N] fp32 -> Wt hi/lo [N,K] bf16 (validated)
// ---------------------------------------------------------------------------
__global__ __launch_bounds__(256)
void conv_t(const float* __restrict__ w, __nv_bfloat16* __restrict__ th,
            __nv_bfloat16* __restrict__ tl, int K, int N)
{
    __shared__ float tile[32][33];
    const int n0 = blockIdx.x * 32, k0 = blockIdx.y * 32;
    const int tx = threadIdx.x, ty = threadIdx.y;
#pragma unroll
    for (int i = 0; i < 4; i++)
        tile[ty + 8 * i][tx] = w[(size_t)(k0 + ty + 8 * i) * N + n0 + tx];
    __syncthreads();
#pragma unroll
    for (int i = 0; i < 4; i++) {
        float v = tile[tx][ty + 8 * i];
        __nv_bfloat16 h, l;
        split_hl(v, h, l);
        size_t o = (size_t)(n0 + ty + 8 * i) * K + k0 + tx;
        th[o] = h;
        tl[o] = l;
    }
}

// ---------------------------------------------------------------------------
// bf16x2-split MMA GEMM, 2-stage cp.async pipeline, templated epilogue.
// MODE 0: C fp32.  MODE 1: rope(+scale)+split -> Dh/Dl bf16 (rope iff
// n0 < rope_limit; tile cols = one head since tiles are 128-aligned).
// ---------------------------------------------------------------------------
#define GP_MATE 5120
#define GP_STGE (4 * GP_MATE)
#define GP_SMEM (2 * GP_STGE * 2)

template<int MODE>
__global__ __launch_bounds__(256)
void gemm_pipe(const __nv_bfloat16* __restrict__ Ah, const __nv_bfloat16* __restrict__ Al,
               const __nv_bfloat16* __restrict__ Bh, const __nv_bfloat16* __restrict__ Bl,
               float* __restrict__ C,
               __nv_bfloat16* __restrict__ Dh, __nv_bfloat16* __restrict__ Dl,
               const float* __restrict__ ctab, const float* __restrict__ stab,
               int M, int N, int K, int dstride, float scale, int rope_limit)
{
    extern __shared__ __nv_bfloat16 smg[];
    const uint32_t smbase = s2u(smg);

    const int tid  = threadIdx.x;
    const int lane = tid & 31;
    const int wid  = tid >> 5;
    const int m0 = blockIdx.y * 128, n0 = blockIdx.x * 128;
    const int wm = (wid & 1) * 64;
    const int wn = (wid >> 1) * 32;

    const int r0 = tid >> 2;
    const int o0 = (tid & 3) * 8;
    const int r1 = r0 + 64;

    float acc[4][4][4];
#pragma unroll
    for (int a = 0; a < 4; a++)
#pragma unroll
        for (int b = 0; b < 4; b++)
#pragma unroll
            for (int c = 0; c < 4; c++) acc[a][b][c] = 0.f;

    const int a_row = ((lane >> 3) & 1) * 8 + (lane & 7);
    const int a_col = (lane >> 4) * 8;
    const int b_row = ((lane >> 4) & 1) * 8 + (lane & 7);
    const int b_col = ((lane >> 3) & 1) * 8;

    const int NI = K / 32;

#define GP_ISSUE(st, kk0)                                                       \
    do {                                                                        \
        const uint32_t sb = smbase + (st) * (GP_STGE * 2);                      \
        cpa16(sb + (r0 * 40 + o0) * 2, Ah + (size_t)(m0 + r0) * K + (kk0) + o0);\
        cpa16(sb + (r1 * 40 + o0) * 2, Ah + (size_t)(m0 + r1) * K + (kk0) + o0);\
        cpa16(sb + (GP_MATE + r0 * 40 + o0) * 2,                                \
              Al + (size_t)(m0 + r0) * K + (kk0) + o0);                         \
        cpa16(sb + (GP_MATE + r1 * 40 + o0) * 2,                                \
              Al + (size_t)(m0 + r1) * K + (kk0) + o0);                         \
        cpa16(sb + (2 * GP_MATE + r0 * 40 + o0) * 2,                            \
              Bh + (size_t)(n0 + r0) * K + (kk0) + o0);                         \
        cpa16(sb + (2 * GP_MATE + r1 * 40 + o0) * 2,                            \
              Bh + (size_t)(n0 + r1) * K + (kk0) + o0);                         \
        cpa16(sb + (3 * GP_MATE + r0 * 40 + o0) * 2,                            \
              Bl + (size_t)(n0 + r0) * K + (kk0) + o0);                         \
        cpa16(sb + (3 * GP_MATE + r1 * 40 + o0) * 2,                            \
              Bl + (size_t)(n0 + r1) * K + (kk0) + o0);                         \
        asm volatile("cp.async.commit_group;");                                 \
    } while (0)

    GP_ISSUE(0, 0);

    for (int it = 0; it < NI; it++) {
        const int st = it & 1;
        if (it + 1 < NI) {
            GP_ISSUE(it & 1 ? 0 : 1, (it + 1) * 32);
            asm volatile("cp.async.wait_group 1;");
        } else {
            asm volatile("cp.async.wait_group 0;");
        }
        __syncthreads();

        const __nv_bfloat16* pAh = smg + st * GP_STGE;
        const __nv_bfloat16* pAl = pAh + GP_MATE;
        const __nv_bfloat16* pBh = pAh + 2 * GP_MATE;
        const __nv_bfloat16* pBl = pAh + 3 * GP_MATE;

#pragma unroll
        for (int kk = 0; kk < 32; kk += 16) {
            uint32_t ah[4][4], al[4][4], bh[4][2], bl[4][2];
#pragma unroll
            for (int mi = 0; mi < 4; mi++) {
                ldmx4(ah[mi][0], ah[mi][1], ah[mi][2], ah[mi][3],
                      s2u(pAh + (wm + 16 * mi + a_row) * 40 + kk + a_col));
                ldmx4(al[mi][0], al[mi][1], al[mi][2], al[mi][3],
                      s2u(pAl + (wm + 16 * mi + a_row) * 40 + kk + a_col));
            }
#pragma unroll
            for (int nj = 0; nj < 2; nj++) {
                uint32_t t0, t1, t2, t3;
                ldmx4(t0, t1, t2, t3,
                      s2u(pBh + (wn + 16 * nj + b_row) * 40 + kk + b_col));
                bh[2 * nj][0] = t0; bh[2 * nj][1] = t1;
                bh[2 * nj + 1][0] = t2; bh[2 * nj + 1][1] = t3;
                ldmx4(t0, t1, t2, t3,
                      s2u(pBl + (wn + 16 * nj + b_row) * 40 + kk + b_col));
                bl[2 * nj][0] = t0; bl[2 * nj][1] = t1;
                bl[2 * nj + 1][0] = t2; bl[2 * nj + 1][1] = t3;
            }
#pragma unroll
            for (int mi = 0; mi < 4; mi++)
#pragma unroll
                for (int ni = 0; ni < 4; ni++) {
                    mma16816(acc[mi][ni], ah[mi][0], ah[mi][1], ah[mi][2], ah[mi][3],
                             bh[ni][0], bh[ni][1]);
                    mma16816(acc[mi][ni], ah[mi][0], ah[mi][1], ah[mi][2], ah[mi][3],
                             bl[ni][0], bl[ni][1]);
                    mma16816(acc[mi][ni], al[mi][0], al[mi][1], al[mi][2], al[mi][3],
                             bh[ni][0], bh[ni][1]);
                }
        }
        __syncthreads();
    }
#undef GP_ISSUE

    const int g  = lane >> 2;
    const int t2 = (lane & 3) * 2;

    if (MODE == 0) {
#pragma unroll
        for (int mi = 0; mi < 4; mi++)
#pragma unroll
            for (int ni = 0; ni < 4; ni++) {
                const int row = m0 + wm + 16 * mi + g;
                const int col = n0 + wn + 8 * ni + t2;
                *(float2*)&C[(size_t)row * N + col] =
                    make_float2(acc[mi][ni][0], acc[mi][ni][1]);
                *(float2*)&C[(size_t)(row + 8) * N + col] =
                    make_float2(acc[mi][ni][2], acc[mi][ni][3]);
            }
    } else {
        // stage fp32 tile to smem (stride 132), then rope+scale+split
        float* ft = (float*)smg;
        __syncthreads();
#pragma unroll
        for (int mi = 0; mi < 4; mi++)
#pragma unroll
            for (int ni = 0; ni < 4; ni++) {
                const int rr = wm + 16 * mi + g;
                const int cc = wn + 8 * ni + t2;
                ft[rr * 132 + cc]           = acc[mi][ni][0];
                ft[rr * 132 + cc + 1]       = acc[mi][ni][1];
                ft[(rr + 8) * 132 + cc]     = acc[mi][ni][2];
                ft[(rr + 8) * 132 + cc + 1] = acc[mi][ni][3];
            }
        __syncthreads();

        const int r  = tid >> 1;           // 0..127
        const int jh = (tid & 1) * 32;     // 0 or 32
        const int t  = m0 + r;             // sequence position
        const bool dorope = (n0 < rope_limit);
        const float* crow = ctab + t * 64;
        const float* srow = stab + t * 64;

#pragma unroll
        for (int blk = 0; blk < 4; blk++) {
            __nv_bfloat16 h0[8], l0[8], h1[8], l1[8];
#pragma unroll
            for (int jj = 0; jj < 8; jj++) {
                const int j = jh + blk * 8 + jj;
                float a = ft[r * 132 + j];
                float b = ft[r * 132 + j + 64];
                float na, nb;
                if (dorope) {
                    const float c = crow[j], s = srow[j];
                    na = a * c - b * s;
                    nb = b * c + a * s;
                } else { na = a; nb = b; }
                na *= scale; nb *= scale;
                split_hl(na, h0[jj], l0[jj]);
                split_hl(nb, h1[jj], l1[jj]);
            }
            const size_t base = (size_t)t * dstride + n0 + jh + blk * 8;
            *(uint4*)(Dh + base)      = *(uint4*)h0;
            *(uint4*)(Dl + base)      = *(uint4*)l0;
            *(uint4*)(Dh + base + 64) = *(uint4*)h1;
            *(uint4*)(Dl + base + 64) = *(uint4*)l1;
        }
    }
}

// ---------------------------------------------------------------------------
// Flash attention FA2, bf16x2 split, BQ=128, pipelined K/V, bf16 hi/lo out.
// ---------------------------------------------------------------------------
#define FST  136
#define QT   (128 * FST)
#define KVT  (64 * FST)
#define F3_SMEM ((2 * QT + 8 * KVT) * 2)

__global__ __launch_bounds__(256)
void flash3(const __nv_bfloat16* __restrict__ Qh, const __nv_bfloat16* __restrict__ Ql,
            const __nv_bfloat16* __restrict__ KVh, const __nv_bfloat16* __restrict__ KVl,
            __nv_bfloat16* __restrict__ AOh, __nv_bfloat16* __restrict__ AOl)
{
    extern __shared__ __nv_bfloat16 smf[];
    __nv_bfloat16* sQh = smf;
    __nv_bfloat16* sQl = sQh + QT;
    __nv_bfloat16* sKV = sQl + QT;
    const uint32_t kvbase = s2u(sKV);

    const int tid  = threadIdx.x;
    const int lane = tid & 31;
    const int wid  = tid >> 5;
    const int wm   = wid * 16;
    const int qb   = blockIdx.x;
    const int h    = blockIdx.y;
    const int kh   = h >> 2;

    const int a_row = ((lane >> 3) & 1) * 8 + (lane & 7);
    const int a_col = (lane >> 4) * 8;
    const int b_row = ((lane >> 4) & 1) * 8 + (lane & 7);
    const int b_col = ((lane >> 3) & 1) * 8;
    const int v_row = lane & 15;
    const int v_col = (lane >> 4) * 8;
    const int g     = lane >> 2;
    const int t2    = (lane & 3) * 2;

    const int qr = tid >> 1;
    const int qc = (tid & 1) * 64;
    {
        const __nv_bfloat16* gq0 = Qh + (size_t)(qb * 128 + qr) * D_MODEL + h * HD + qc;
        const __nv_bfloat16* gq1 = Ql + (size_t)(qb * 128 + qr) * D_MODEL + h * HD + qc;
#pragma unroll
        for (int i = 0; i < 8; i++) {
            *(uint4*)&sQh[qr * FST + qc + i * 8] = *(const uint4*)(gq0 + i * 8);
            *(uint4*)&sQl[qr * FST + qc + i * 8] = *(const uint4*)(gq1 + i * 8);
        }
    }

    const int kr = tid >> 2;
    const int kc = (tid & 3) * 32;
    const int ntiles = 2 * qb + 2;

#define F3_ISSUE(jtv)                                                            \
    do {                                                                         \
        const int _st = (jtv) & 1;                                               \
        const int _j0 = (jtv) * 64;                                              \
        const uint32_t sb = kvbase + _st * (4 * KVT) * 2;                        \
        const __nv_bfloat16* khg = KVh + (size_t)(_j0 + kr) * KV2 + kh * HD + kc;\
        const __nv_bfloat16* klg = KVl + (size_t)(_j0 + kr) * KV2 + kh * HD + kc;\
        const __nv_bfloat16* vhg = khg + KV_DIM;                                 \
        const __nv_bfloat16* vlg = klg + KV_DIM;                                 \
        _Pragma("unroll")                                                        \
        for (int i = 0; i < 4; i++) {                                            \
            const uint32_t so = (kr * FST + kc + i * 8) * 2;                     \
            cpa16(sb + so,               khg + i * 8);                           \
            cpa16(sb + KVT * 2 + so,     klg + i * 8);                           \
            cpa16(sb + 2 * KVT * 2 + so, vhg + i * 8);                           \
            cpa16(sb + 3 * KVT * 2 + so, vlg + i * 8);                           \
        }                                                                        \
        asm volatile("cp.async.commit_group;");                                  \
    } while (0)

    float o[16][4];
#pragma unroll
    for (int i = 0; i < 16; i++)
#pragma unroll
        for (int j = 0; j < 4; j++) o[i][j] = 0.f;
    float m0r = -1e30f, m1r = -1e30f, l0r = 0.f, l1r = 0.f;

    F3_ISSUE(0);

    for (int jt = 0; jt < ntiles; jt++) {
        const int st = jt & 1;
        const int j0 = jt * 64;
        if (jt + 1 < ntiles) {
            F3_ISSUE(jt + 1);
            asm volatile("cp.async.wait_group 1;");
        } else {
            asm volatile("cp.async.wait_group 0;");
        }
        __syncthreads();

        const __nv_bfloat16* sKh = sKV + st * 4 * KVT;
        const __nv_bfloat16* sKl = sKh + KVT;
        const __nv_bfloat16* sVh = sKh + 2 * KVT;
        const __nv_bfloat16* sVl = sKh + 3 * KVT;

        float sa[8][4];
#pragma unroll
        for (int c = 0; c < 8; c++)
#pragma unroll
            for (int j = 0; j < 4; j++) sa[c][j] = 0.f;

#pragma unroll
        for (int kk = 0; kk < 8; kk++) {
            uint32_t qh0, qh1, qh2, qh3, ql0, ql1, ql2, ql3;
            ldmx4(qh0, qh1, qh2, qh3, s2u(&sQh[(wm + a_row) * FST + kk * 16 + a_col]));
            ldmx4(ql0, ql1, ql2, ql3, s2u(&sQl[(wm + a_row) * FST + kk * 16 + a_col]));
#pragma unroll
            for (int njp = 0; njp < 4; njp++) {
                uint32_t bh0, bh1, bh2, bh3, bl0, bl1, bl2, bl3;
                ldmx4(bh0, bh1, bh2, bh3,
                      s2u(sKh + (njp * 16 + b_row) * FST + kk * 16 + b_col));
                ldmx4(bl0, bl1, bl2, bl3,
                      s2u(sKl + (njp * 16 + b_row) * FST + kk * 16 + b_col));
                mma16816(sa[2 * njp], qh0, qh1, qh2, qh3, bh0, bh1);
                mma16816(sa[2 * njp], qh0, qh1, qh2, qh3, bl0, bl1);
                mma16816(sa[2 * njp], ql0, ql1, ql2, ql3, bh0, bh1);
                mma16816(sa[2 * njp + 1], qh0, qh1, qh2, qh3, bh2, bh3);
                mma16816(sa[2 * njp + 1], qh0, qh1, qh2, qh3, bl2, bl3);
                mma16816(sa[2 * njp + 1], ql0, ql1, ql2, ql3, bh2, bh3);
            }
        }

        if (jt >= ntiles - 2) {
            const int qr0 = qb * 128 + wm + g;
            const int qr1 = qr0 + 8;
#pragma unroll
            for (int c = 0; c < 8; c++) {
                const int col = j0 + c * 8 + t2;
                if (col     > qr0) sa[c][0] = -1e30f;
                if (col + 1 > qr0) sa[c][1] = -1e30f;
                if (col     > qr1) sa[c][2] = -1e30f;
                if (col + 1 > qr1) sa[c][3] = -1e30f;
            }
        }

        float rm0 = -1e30f, rm1 = -1e30f;
#pragma unroll
        for (int c = 0; c < 8; c++) {
            rm0 = fmaxf(rm0, fmaxf(sa[c][0], sa[c][1]));
            rm1 = fmaxf(rm1, fmaxf(sa[c][2], sa[c][3]));
        }
        rm0 = fmaxf(rm0, __shfl_xor_sync(0xffffffffu, rm0, 1));
        rm0 = fmaxf(rm0, __shfl_xor_sync(0xffffffffu, rm0, 2));
        rm1 = fmaxf(rm1, __shfl_xor_sync(0xffffffffu, rm1, 1));
        rm1 = fmaxf(rm1, __shfl_xor_sync(0xffffffffu, rm1, 2));

        const float mn0 = fmaxf(m0r, rm0);
        const float mn1 = fmaxf(m1r, rm1);
        const float al0 = __expf(m0r - mn0);
        const float al1 = __expf(m1r - mn1);

        float rs0 = 0.f, rs1 = 0.f;
#pragma unroll
        for (int c = 0; c < 8; c++) {
            sa[c][0] = __expf(sa[c][0] - mn0);
            sa[c][1] = __expf(sa[c][1] - mn0);
            sa[c][2] = __expf(sa[c][2] - mn1);
            sa[c][3] = __expf(sa[c][3] - mn1);
            rs0 += sa[c][0] + sa[c][1];
            rs1 += sa[c][2] + sa[c][3];
        }
        rs0 += __shfl_xor_sync(0xffffffffu, rs0, 1);
        rs0 += __shfl_xor_sync(0xffffffffu, rs0, 2);
        rs1 += __shfl_xor_sync(0xffffffffu, rs1, 1);
        rs1 += __shfl_xor_sync(0xffffffffu, rs1, 2);

        l0r = l0r * al0 + rs0;
        l1r = l1r * al1 + rs1;
        m0r = mn0;
        m1r = mn1;
#pragma unroll
        for (int dj = 0; dj < 16; dj++) {
            o[dj][0] *= al0;
            o[dj][1] *= al0;
            o[dj][2] *= al1;
            o[dj][3] *= al1;
        }

#pragma unroll
        for (int ks = 0; ks < 4; ks++) {
            const int c0 = 2 * ks, c1 = 2 * ks + 1;
            uint32_t pl0, pl1, pl2, pl3;
            const uint32_t ph0 = pack_hl(sa[c0][0], sa[c0][1], pl0);
            const uint32_t ph1 = pack_hl(sa[c0][2], sa[c0][3], pl1);
            const uint32_t ph2 = pack_hl(sa[c1][0], sa[c1][1], pl2);
            const uint32_t ph3 = pack_hl(sa[c1][2], sa[c1][3], pl3);
#pragma unroll
            for (int djp = 0; djp < 8; djp++) {
                uint32_t vh0, vh1, vh2, vh3, vl0, vl1, vl2, vl3;
                ldmx4t(vh0, vh1, vh2, vh3,
                       s2u(sVh + (ks * 16 + v_row) * FST + djp * 16 + v_col));
                ldmx4t(vl0, vl1, vl2, vl3,
                       s2u(sVl + (ks * 16 + v_row) * FST + djp * 16 + v_col));
                mma16816(o[2 * djp], ph0, ph1, ph2, ph3, vh0, vh1);
                mma16816(o[2 * djp], ph0, ph1, ph2, ph3, vl0, vl1);
                mma16816(o[2 * djp], pl0, pl1, pl2, pl3, vh0, vh1);
                mma16816(o[2 * djp + 1], ph0, ph1, ph2, ph3, vh2, vh3);
                mma16816(o[2 * djp + 1], ph0, ph1, ph2, ph3, vl2, vl3);
                mma16816(o[2 * djp + 1], pl0, pl1, pl2, pl3, vh2, vh3);
            }
        }
        __syncthreads();
    }
#undef F3_ISSUE

    // epilogue: normalize + hi/lo split directly to bf16
    const float inv0 = 1.0f / l0r;
    const float inv1 = 1.0f / l1r;
    const int row0 = qb * 128 + wm + g;
    const int row1 = row0 + 8;
#pragma unroll
    for (int dj = 0; dj < 16; dj++) {
        uint32_t lo;
        uint32_t hi = pack_hl(o[dj][0] * inv0, o[dj][1] * inv0, lo);
        const size_t b0 = (size_t)row0 * D_MODEL + h * HD + dj * 8 + t2;
        *(uint32_t*)(AOh + b0) = hi;
        *(uint32_t*)(AOl + b0) = lo;
        hi = pack_hl(o[dj][2] * inv1, o[dj][3] * inv1, lo);
        const size_t b1 = (size_t)row1 * D_MODEL + h * HD + dj * 8 + t2;
        *(uint32_t*)(AOh + b1) = hi;
        *(uint32_t*)(AOl + b1) = lo;
    }
}

// ---------------------------------------------------------------------------
// launch — signature order: x, wq, wk, wv, wo
// ---------------------------------------------------------------------------
extern "C" void kernel_launch(void* const* d_in, const int* in_sizes, int n_in,
                              void* d_out, int out_size)
{
    const float* x  = (const float*)d_in[0];
    const float* wq = (const float*)d_in[1];
    const float* wk = (const float*)d_in[2];
    const float* wv = (const float*)d_in[3];
    const float* wo = (const float*)d_in[4];
    float* out = (float*)d_out;

    __nv_bfloat16 *xh, *xl, *aoh, *aol, *wqh, *wql, *wkvh, *wkvl, *woh, *wol;
    __nv_bfloat16 *qhh, *qll, *kvh, *kvl;
    float *ct, *st;
    cudaGetSymbolAddress((void**)&xh,   g_xh);   cudaGetSymbolAddress((void**)&xl,   g_xl);
    cudaGetSymbolAddress((void**)&aoh,  g_aoh);  cudaGetSymbolAddress((void**)&aol,  g_aol);
    cudaGetSymbolAddress((void**)&wqh,  g_wqh);  cudaGetSymbolAddress((void**)&wql,  g_wql);
    cudaGetSymbolAddress((void**)&wkvh, g_wkvh); cudaGetSymbolAddress((void**)&wkvl, g_wkvl);
    cudaGetSymbolAddress((void**)&woh,  g_woh);  cudaGetSymbolAddress((void**)&wol,  g_wol);
    cudaGetSymbolAddress((void**)&qhh,  g_Qh);   cudaGetSymbolAddress((void**)&qll,  g_Ql);
    cudaGetSymbolAddress((void**)&kvh,  g_KVh);  cudaGetSymbolAddress((void**)&kvl,  g_KVl);
    cudaGetSymbolAddress((void**)&ct,   g_ct);   cudaGetSymbolAddress((void**)&st,   g_st);

    cudaFuncSetAttribute(gemm_pipe<0>, cudaFuncAttributeMaxDynamicSharedMemorySize, GP_SMEM);
    cudaFuncSetAttribute(gemm_pipe<1>, cudaFuncAttributeMaxDynamicSharedMemorySize, GP_SMEM);
    cudaFuncSetAttribute(flash3, cudaFuncAttributeMaxDynamicSharedMemorySize, F3_SMEM);

    // rope tables + conversions
    rope_tab<<<T_SEQ, 64>>>(ct, st);
    conv_hilo8<<<SZ_X / 2048, 256>>>(x, xh, xl, SZ_X);
    conv_t<<<dim3(D_MODEL / 32, D_MODEL / 32), dim3(32, 8)>>>(wq, wqh, wql, D_MODEL, D_MODEL);
    conv_t<<<dim3(KV_DIM / 32, D_MODEL / 32), dim3(32, 8)>>>(wk, wkvh, wkvl, D_MODEL, KV_DIM);
    conv_t<<<dim3(KV_DIM / 32, D_MODEL / 32), dim3(32, 8)>>>(wv, wkvh + (size_t)KV_DIM * D_MODEL,
                                                             wkvl + (size_t)KV_DIM * D_MODEL,
                                                             D_MODEL, KV_DIM);
    conv_t<<<dim3(D_MODEL / 32, D_MODEL / 32), dim3(32, 8)>>>(wo, woh, wol, D_MODEL, D_MODEL);

    // Q projection: fused rope + scale + split
    gemm_pipe<1><<<dim3(D_MODEL / 128, T_SEQ / 128), 256, GP_SMEM>>>(
        xh, xl, wqh, wql, nullptr, qhh, qll, ct, st,
        T_SEQ, D_MODEL, D_MODEL, D_MODEL, SCALE, D_MODEL);

    // KV projection: fused rope (K only) + split
    gemm_pipe<1><<<dim3(KV2 / 128, T_SEQ / 128), 256, GP_SMEM>>>(
        xh, xl, wkvh, wkvl, nullptr, kvh, kvl, ct, st,
        T_SEQ, KV2, D_MODEL, KV2, 1.0f, KV_DIM);

    // attention (writes bf16 hi/lo)
    flash3<<<dim3(T_SEQ / 128, N_HEADS), 256, F3_SMEM>>>(qhh, qll, kvh, kvl, aoh, aol);

    // output projection (fp32 out)
    gemm_pipe<0><<<dim3(D_MODEL / 128, T_SEQ / 128), 256, GP_SMEM>>>(
        aoh, aol, woh, wol, out, nullptr, nullptr, nullptr, nullptr,
        T_SEQ, D_MODEL, D_MODEL, 0, 1.0f, 0);
}